// round 12
// baseline (speedup 1.0000x reference)
#include <cuda_runtime.h>
#include <cuda_bf16.h>
#include <math.h>
#include <stdint.h>

constexpr int BB = 4;
constexpr int SS = 2048;
constexpr int DD = 1024;
constexpr int HH = 16;
constexpr int HD = 64;
constexpr int FF = 4096;
constexpr int MM = BB * SS;

#if defined(__CUDA_ARCH_FEAT_SM103_ALL) || defined(__CUDA_ARCH_FEAT_SM100_ALL)
#define HAS_TCGEN05 1
#else
#define HAS_TCGEN05 0
#endif

// ---------------- device scratch ----------------
__device__ __nv_bfloat16 g_xh[(size_t)MM * DD];
__device__ __nv_bfloat16 g_xl[(size_t)MM * DD];
__device__ __nv_bfloat16 g_qh[(size_t)MM * DD];
__device__ __nv_bfloat16 g_kh[(size_t)MM * DD];
__device__ __nv_bfloat16 g_vh[(size_t)MM * DD];
__device__ __nv_bfloat16 g_vt[(size_t)MM * DD];   // V transposed [B,H,HD,SS]
__device__ __nv_bfloat16 g_oh[(size_t)MM * DD];
__device__ __nv_bfloat16 g_ol[(size_t)MM * DD];
__device__ __nv_bfloat16 g_hb[(size_t)MM * DD];
__device__ __nv_bfloat16 g_hl[(size_t)MM * DD];
__device__ __nv_bfloat16 g_fh[(size_t)MM * FF];
__device__ __nv_bfloat16 g_fl[(size_t)MM * FF];
__device__ float g_f32a[(size_t)MM * DD];
__device__ float g_f32b[(size_t)MM * DD];
__device__ float g_f32c[(size_t)MM * DD];

constexpr size_t WQ_OFF = 0;
constexpr size_t WK_OFF = 1048576;
constexpr size_t WV_OFF = 2097152;
constexpr size_t WO_OFF = 3145728;
constexpr size_t W1_OFF = 4194304;
constexpr size_t W2_OFF = 8388608;
constexpr size_t WTOT   = 12582912;
__device__ __nv_bfloat16 g_wh[WTOT];
__device__ __nv_bfloat16 g_wl[WTOT];

// ---------------- helpers ----------------
__device__ __forceinline__ uint32_t smem_u32(const void* p) {
    uint32_t a;
    asm("{ .reg .u64 t; cvta.to.shared.u64 t, %1; cvt.u32.u64 %0, t; }" : "=r"(a) : "l"(p));
    return a;
}
__device__ __forceinline__ uint32_t swz128(uint32_t off) { return off ^ ((off >> 3) & 0x70); }
__device__ __forceinline__ uint32_t swz64(uint32_t off)  { return off ^ ((off >> 3) & 0x30); }
__device__ __forceinline__ uint32_t pack_bf2(__nv_bfloat16 a, __nv_bfloat16 b) {
    __nv_bfloat162 t; t.x = a; t.y = b; return *(uint32_t*)&t;
}
#define CP_ASYNC16(saddr, gptr) \
    asm volatile("cp.async.cg.shared.global [%0], [%1], 16;" \
        :: "r"((uint32_t)(saddr)), "l"(gptr) : "memory")
#define CP_COMMIT() asm volatile("cp.async.commit_group;" ::: "memory")
#define CP_WAIT(n)  asm volatile("cp.async.wait_group %0;" :: "n"(n) : "memory")

#if HAS_TCGEN05
__device__ __forceinline__ uint32_t elect_one_pred() {
    uint32_t pred;
    asm volatile("{\n\t.reg .pred p;\n\telect.sync _|p, 0xFFFFFFFF;\n\tselp.b32 %0, 1, 0, p;\n\t}" : "=r"(pred));
    return pred;
}
#define TCGEN05_ALLOC(smem_addr, nCols) \
    asm volatile("tcgen05.alloc.cta_group::1.sync.aligned.shared::cta.b32 [%0], %1;" \
        :: "r"((uint32_t)(smem_addr)), "r"((uint32_t)(nCols)) : "memory")
#define TCGEN05_DEALLOC(tmem_addr, nCols) \
    asm volatile("tcgen05.dealloc.cta_group::1.sync.aligned.b32 %0, %1;" \
        :: "r"(tmem_addr), "r"((uint32_t)(nCols)))
#define TCGEN05_COMMIT(mbar) \
    asm volatile("tcgen05.commit.cta_group::1.mbarrier::arrive::one.shared::cluster.b64 [%0];" \
        :: "r"((uint32_t)(mbar)) : "memory")
#define TCGEN05_WAIT_LD()  asm volatile("tcgen05.wait::ld.sync.aligned;" ::: "memory")
#define TCGEN05_FENCE_BEFORE() asm volatile("tcgen05.fence::before_thread_sync;" ::: "memory")
#define TCGEN05_FENCE_AFTER()  asm volatile("tcgen05.fence::after_thread_sync;" ::: "memory")
#define FENCE_ASYNC_SHARED() asm volatile("fence.proxy.async.shared::cta;" ::: "memory")
#define MBARRIER_INIT(mbar, cnt) \
    asm volatile("mbarrier.init.shared.b64 [%0], %1;" :: "r"((uint32_t)(mbar)), "r"((uint32_t)(cnt)) : "memory")
#define MBARRIER_INVAL(mbar) \
    asm volatile("mbarrier.inval.shared.b64 [%0];" :: "r"((uint32_t)(mbar)) : "memory")
#define MBARRIER_WAIT_PARITY(mbar, parity) do {                                    \
    uint32_t _mb = (uint32_t)(mbar);                                               \
    uint32_t _pa = (uint32_t)(parity);                                             \
    uint32_t _done;                                                                \
    asm volatile(                                                                  \
        "{\n\t.reg .pred p;\n\t"                                                   \
        "mbarrier.try_wait.parity.acquire.cta.shared::cta.b64 p, [%1], %2;\n\t"    \
        "selp.b32 %0, 1, 0, p;\n\t}"                                               \
        : "=r"(_done) : "r"(_mb), "r"(_pa) : "memory");                            \
    if (!_done) {                                                                  \
        asm volatile(                                                              \
            "{\n\t.reg .pred P1;\n\t"                                              \
            "WL_%=:\n\t"                                                           \
            "mbarrier.try_wait.parity.acquire.cta.shared::cta.b64 P1, [%0], %1, 0x989680;\n\t" \
            "@P1 bra.uni WD_%=;\n\t"                                               \
            "bra.uni WL_%=;\n\t"                                                   \
            "WD_%=:\n\t}"                                                          \
            :: "r"(_mb), "r"(_pa) : "memory");                                     \
    }                                                                              \
} while (0)
#define TCGEN05_LD_X32(r, addr) \
    asm volatile( \
        "tcgen05.ld.sync.aligned.32x32b.x32.b32 " \
        "{%0, %1, %2, %3, %4, %5, %6, %7, " \
        " %8, %9, %10, %11, %12, %13, %14, %15, " \
        " %16, %17, %18, %19, %20, %21, %22, %23, " \
        " %24, %25, %26, %27, %28, %29, %30, %31}, [%32];" \
        : "=r"((r)[0]),  "=r"((r)[1]),  "=r"((r)[2]),  "=r"((r)[3]), \
          "=r"((r)[4]),  "=r"((r)[5]),  "=r"((r)[6]),  "=r"((r)[7]), \
          "=r"((r)[8]),  "=r"((r)[9]),  "=r"((r)[10]), "=r"((r)[11]), \
          "=r"((r)[12]), "=r"((r)[13]), "=r"((r)[14]), "=r"((r)[15]), \
          "=r"((r)[16]), "=r"((r)[17]), "=r"((r)[18]), "=r"((r)[19]), \
          "=r"((r)[20]), "=r"((r)[21]), "=r"((r)[22]), "=r"((r)[23]), \
          "=r"((r)[24]), "=r"((r)[25]), "=r"((r)[26]), "=r"((r)[27]), \
          "=r"((r)[28]), "=r"((r)[29]), "=r"((r)[30]), "=r"((r)[31]) \
        : "r"(addr))

__device__ __forceinline__ uint64_t make_desc_sw128(uint32_t addr) {
    constexpr uint64_t BASE =
        (uint64_t(2) << 61) | (uint64_t(1) << 46) | (uint64_t(64) << 32) | (uint64_t(1) << 16);
    return BASE | ((uint64_t)(addr >> 4) & 0x3FFF);
}
// SW64: layout=4, version=1, SBO=32 (512B = 8 rows x 64B), LBO=1
__device__ __forceinline__ uint64_t make_desc_sw64(uint32_t addr) {
    constexpr uint64_t BASE =
        (uint64_t(4) << 61) | (uint64_t(1) << 46) | (uint64_t(32) << 32) | (uint64_t(1) << 16);
    return BASE | ((uint64_t)(addr >> 4) & 0x3FFF);
}
__device__ __forceinline__ void mma_bf16_ss(uint32_t d, uint64_t ad, uint64_t bd,
                                            uint32_t idesc, bool acc) {
    uint32_t en = acc ? 1u : 0u;
    asm volatile(
        "{\n\t.reg .pred p;\n\t"
        "setp.ne.u32 p, %5, 0;\n\t"
        "tcgen05.mma.cta_group::1.kind::f16 [%0], %1, %2, %3, {%4, %4, %4, %4}, p;\n\t}"
        :: "r"(d), "l"(ad), "l"(bd), "r"(idesc), "r"(0u), "r"(en) : "memory");
}
#endif

constexpr uint32_t GEMM_IDESC =        // M=128, N=128 (flash)
    (1u << 4) | (1u << 7) | (1u << 10) | ((128 / 8) << 17) | ((128 / 16) << 24);
constexpr uint32_t IDESC_N64 =         // M=128, N=64 (flash PV)
    (1u << 4) | (1u << 7) | (1u << 10) | ((64 / 8) << 17) | ((128 / 16) << 24);
constexpr uint32_t IDESC_N256 =        // M=128, N=256 (GEMM)
    (1u << 4) | (1u << 7) | (1u << 10) | ((256 / 8) << 17) | ((128 / 16) << 24);

// ---------------- weight prep ----------------
__global__ void prep_w_kernel(const float* __restrict__ W,
                              __nv_bfloat16* __restrict__ Bh,
                              __nv_bfloat16* __restrict__ Bl, int K, int N)
{
    __shared__ float t[32][33];
    const int n0 = blockIdx.x * 32, k0 = blockIdx.y * 32;
#pragma unroll
    for (int i = 0; i < 4; i++)
        t[threadIdx.y + i * 8][threadIdx.x] =
            W[(size_t)(k0 + threadIdx.y + i * 8) * N + n0 + threadIdx.x];
    __syncthreads();
#pragma unroll
    for (int i = 0; i < 4; i++) {
        int n = threadIdx.y + i * 8;
        float v = t[threadIdx.x][n];
        __nv_bfloat16 h = __float2bfloat16(v);
        size_t idx = (size_t)(n0 + n) * K + k0 + threadIdx.x;
        Bh[idx] = h;
        Bl[idx] = __float2bfloat16(v - __bfloat162float(h));
    }
}

// fp32 -> bf16 hi/lo split
__global__ __launch_bounds__(256) void split_kernel(
    const float* __restrict__ in,
    __nv_bfloat16* __restrict__ oh, __nv_bfloat16* __restrict__ ol)
{
    size_t i = ((size_t)blockIdx.x * 256 + threadIdx.x) * 4;
    float4 v = *(const float4*)(in + i);
    __nv_bfloat16 h0 = __float2bfloat16(v.x), h1 = __float2bfloat16(v.y);
    __nv_bfloat16 h2 = __float2bfloat16(v.z), h3 = __float2bfloat16(v.w);
    *(uint2*)(oh + i) = make_uint2(pack_bf2(h0, h1), pack_bf2(h2, h3));
    *(uint2*)(ol + i) = make_uint2(
        pack_bf2(__float2bfloat16(v.x - __bfloat162float(h0)),
                 __float2bfloat16(v.y - __bfloat162float(h1))),
        pack_bf2(__float2bfloat16(v.z - __bfloat162float(h2)),
                 __float2bfloat16(v.w - __bfloat162float(h3))));
}

// V transpose: vh [BH][SS][HD] -> vt [BH][HD][SS]
__global__ __launch_bounds__(256) void transpose_v_kernel(
    const __nv_bfloat16* __restrict__ vh, __nv_bfloat16* __restrict__ vt)
{
    __shared__ __nv_bfloat16 t[64][72];
    const int bh = blockIdx.y;
    const int s0 = blockIdx.x * 64;
    const int r = threadIdx.x >> 2;
    const int c = (threadIdx.x & 3) * 16;
    const __nv_bfloat16* src = vh + ((size_t)(bh * SS + s0 + r)) * HD + c;
    *(uint4*)(&t[r][c])     = *(const uint4*)(src);
    *(uint4*)(&t[r][c + 8]) = *(const uint4*)(src + 8);
    __syncthreads();
    __nv_bfloat16* dst = vt + ((size_t)(bh * HD + r)) * SS + s0 + c;
    __nv_bfloat16 tmp[16];
#pragma unroll
    for (int j = 0; j < 16; j++) tmp[j] = t[c + j][r];
    *(uint4*)(dst)     = *(uint4*)(tmp);
    *(uint4*)(dst + 8) = *(uint4*)(tmp + 8);
}

// ---------------------------------------------------------------------------
// GEMM: 256x256 CTA tile, SW64 staging, K-chunks of 32, 3-stage cp.async.
// Stage (64KB): Ah 16K (256 rows x 64B) | Al 16K | Bh 16K | Bl 16K
// MMA: N=256 per dispatch; two M=128 tiles -> TMEM cols 0 and 256.
// ---------------------------------------------------------------------------
constexpr int GEMM_STAGE = 65536;
constexpr int GEMM_SMEM_BYTES = 3 * GEMM_STAGE + 1024;

template <int EPI>
__global__ __launch_bounds__(256, 1) void gemm_bf(
    const __nv_bfloat16* __restrict__ Ah, const __nv_bfloat16* __restrict__ Al,
    const __nv_bfloat16* __restrict__ Bh, const __nv_bfloat16* __restrict__ Bl,
    float* __restrict__ Cf, __nv_bfloat16* __restrict__ Ch, __nv_bfloat16* __restrict__ Cl,
    __nv_bfloat16* __restrict__ D0, __nv_bfloat16* __restrict__ D1, __nv_bfloat16* __restrict__ D2,
    const float* __restrict__ bias0, const float* __restrict__ bias1, const float* __restrict__ bias2,
    int M, int N, int K)
{
    extern __shared__ char dsmem[];
    uintptr_t p = ((uintptr_t)dsmem + 1023) & ~(uintptr_t)1023;
    char* buf = (char*)p;
    const int tid = threadIdx.x;
    const int wid = tid >> 5;
    const int lane = tid & 31;
    const int m0 = blockIdx.y << 8;   // 256-row tile
    const int n0 = blockIdx.x << 8;   // 256-col tile

#if HAS_TCGEN05
    __shared__ alignas(16) unsigned long long ctrlq[5];
    const uint32_t sbuf = smem_u32(buf);
    const uint32_t ctrl = smem_u32(ctrlq);

    if (wid == 0) TCGEN05_ALLOC(ctrl, 512);
    if (tid == 0) {
        MBARRIER_INIT(ctrl + 8, 1);
        MBARRIER_INIT(ctrl + 16, 1);
        MBARRIER_INIT(ctrl + 24, 1);
        MBARRIER_INIT(ctrl + 32, 1);
    }
    __syncthreads();
    uint32_t tmem;
    asm volatile("ld.shared.b32 %0, [%1];" : "=r"(tmem) : "r"(ctrl));

    const int NC = K >> 5;   // K-chunks of 32

    auto load_chunk = [&](int ck, int st) {
        const uint32_t sb = sbuf + (uint32_t)st * GEMM_STAGE;
        const int k0 = ck << 5;
        // A hi/lo: 256 rows x 4 groups of 16B
#pragma unroll
        for (int j = 0; j < 4; j++) {
            int u = tid + j * 256;
            int r = u >> 2, g = u & 3;
            uint32_t so = swz64((uint32_t)(r * 64 + g * 16));
            size_t ao = (size_t)(m0 + r) * K + k0 + g * 8;
            CP_ASYNC16(sb + so,         Ah + ao);
            CP_ASYNC16(sb + 16384 + so, Al + ao);
        }
        // B hi/lo: 256 rows x 4 groups of 16B
#pragma unroll
        for (int j = 0; j < 4; j++) {
            int u = tid + j * 256;
            int r = u >> 2, g = u & 3;
            uint32_t so = swz64((uint32_t)(r * 64 + g * 16));
            size_t bo = (size_t)(n0 + r) * K + k0 + g * 8;
            CP_ASYNC16(sb + 32768 + so, Bh + bo);
            CP_ASYNC16(sb + 49152 + so, Bl + bo);
        }
    };

    // prologue: fill 3 stages
#pragma unroll
    for (int s = 0; s < 3; s++) { load_chunk(s, s); CP_COMMIT(); }

    int ph[3] = {0, 0, 0};

    for (int i = 0; i < NC; i++) {
        const int st = i % 3;
        if (i < NC - 2)       CP_WAIT(2);
        else if (i == NC - 2) CP_WAIT(1);
        else                  CP_WAIT(0);
        __syncthreads();
        FENCE_ASYNC_SHARED();

        if (wid == 0 && elect_one_pred()) {
            const uint32_t sb = sbuf + (uint32_t)st * GEMM_STAGE;
            uint64_t dBh = make_desc_sw64(sb + 32768);
            uint64_t dBl = make_desc_sw64(sb + 49152);
#pragma unroll
            for (int mt = 0; mt < 2; mt++) {
                // A M-tile: rows [mt*128, mt*128+128) -> +8192 bytes = +512 units
                uint64_t dAh = make_desc_sw64(sb + mt * 8192);
                uint64_t dAl = make_desc_sw64(sb + 16384 + mt * 8192);
                uint32_t dst = tmem + mt * 256;
#pragma unroll
                for (int ks = 0; ks < 2; ks++)
                    mma_bf16_ss(dst, dAh + ks * 2, dBh + ks * 2, IDESC_N256, !(i == 0 && ks == 0));
#pragma unroll
                for (int ks = 0; ks < 2; ks++)
                    mma_bf16_ss(dst, dAl + ks * 2, dBh + ks * 2, IDESC_N256, true);
#pragma unroll
                for (int ks = 0; ks < 2; ks++)
                    mma_bf16_ss(dst, dAh + ks * 2, dBl + ks * 2, IDESC_N256, true);
            }
            TCGEN05_COMMIT(ctrl + 8 + st * 8);
        }

        int ni = i + 3;
        if (ni < NC) {
            MBARRIER_WAIT_PARITY(ctrl + 8 + st * 8, ph[st]);
            ph[st] ^= 1;
            load_chunk(ni, st);
            CP_COMMIT();
        }
    }

    if (wid == 0 && elect_one_pred()) TCGEN05_COMMIT(ctrl + 32);
    MBARRIER_WAIT_PARITY(ctrl + 32, 0);
    TCGEN05_FENCE_AFTER();

    // epilogue: 8 warps; each warp: rows sp*32+lane, col-chunks nh = chf, chf+2
    {
        const int sp = wid & 3;
        const int chf = wid >> 2;
#pragma unroll
        for (int mt = 0; mt < 2; mt++) {
            for (int nh = chf; nh < 4; nh += 2) {
                uint32_t r[64];
                TCGEN05_LD_X32(r, tmem + mt * 256 + nh * 64);
                TCGEN05_LD_X32(r + 32, tmem + mt * 256 + nh * 64 + 32);
                TCGEN05_WAIT_LD();
                TCGEN05_FENCE_BEFORE();

                const int row = m0 + mt * 128 + sp * 32 + lane;
                const int c0 = n0 + nh * 64;

                if (EPI == 0) {
                    float* cp = Cf + (size_t)row * N + c0;
#pragma unroll
                    for (int c = 0; c < 16; c++) {
                        float4 v;
                        v.x = __uint_as_float(r[4 * c + 0]);
                        v.y = __uint_as_float(r[4 * c + 1]);
                        v.z = __uint_as_float(r[4 * c + 2]);
                        v.w = __uint_as_float(r[4 * c + 3]);
                        *(float4*)(cp + 4 * c) = v;
                    }
                } else if (EPI == 1) {
                    size_t base = (size_t)row * N + c0;
#pragma unroll
                    for (int j8 = 0; j8 < 8; j8++) {
                        uint32_t hw[4], lw[4];
#pragma unroll
                        for (int q = 0; q < 4; q++) {
                            int j = j8 * 8 + q * 2;
                            float v0 = fmaxf(__uint_as_float(r[j])     + bias0[c0 + j],     0.0f);
                            float v1 = fmaxf(__uint_as_float(r[j + 1]) + bias0[c0 + j + 1], 0.0f);
                            __nv_bfloat16 h0 = __float2bfloat16(v0), h1 = __float2bfloat16(v1);
                            hw[q] = pack_bf2(h0, h1);
                            lw[q] = pack_bf2(__float2bfloat16(v0 - __bfloat162float(h0)),
                                             __float2bfloat16(v1 - __bfloat162float(h1)));
                        }
                        *(uint4*)(Ch + base + j8 * 8) = make_uint4(hw[0], hw[1], hw[2], hw[3]);
                        *(uint4*)(Cl + base + j8 * 8) = make_uint4(lw[0], lw[1], lw[2], lw[3]);
                    }
                } else {  // EPI == 2
                    const int mat = c0 >> 10;
                    const int lc = c0 & 1023;
                    const float* bs = (mat == 0) ? bias0 : (mat == 1) ? bias1 : bias2;
                    __nv_bfloat16* Dd = (mat == 0) ? D0 : (mat == 1) ? D1 : D2;
                    const int h_ = lc >> 6;
                    const int b_ = row >> 11;
                    const int s_ = row & (SS - 1);
                    size_t base = (((size_t)b_ * HH + h_) * SS + s_) * HD;
#pragma unroll
                    for (int j8 = 0; j8 < 8; j8++) {
                        uint32_t hw[4];
#pragma unroll
                        for (int q = 0; q < 4; q++) {
                            int j = j8 * 8 + q * 2;
                            float v0 = __uint_as_float(r[j])     + bs[lc + j];
                            float v1 = __uint_as_float(r[j + 1]) + bs[lc + j + 1];
                            hw[q] = pack_bf2(__float2bfloat16(v0), __float2bfloat16(v1));
                        }
                        *(uint4*)(Dd + base + j8 * 8) = make_uint4(hw[0], hw[1], hw[2], hw[3]);
                    }
                }
            }
        }
    }

    __syncthreads();
    if (tid == 0) {
        MBARRIER_INVAL(ctrl + 8);
        MBARRIER_INVAL(ctrl + 16);
        MBARRIER_INVAL(ctrl + 24);
        MBARRIER_INVAL(ctrl + 32);
    }
    __syncthreads();
    if (wid == 0) TCGEN05_DEALLOC(tmem, 512);

#else  // FFMA fallback (256x256 via 4 sub-tiles)
    float* As = (float*)buf;
    float* Bs = As + 16 * 132;
    const int tx = tid & 15, ty = tid >> 4;
    for (int mt = 0; mt < 2; mt++)
    for (int nt = 0; nt < 2; nt++) {
        const int mb = m0 + mt * 128;
        const int nb = n0 + nt * 128;
        float acc[8][8];
#pragma unroll
        for (int i = 0; i < 8; i++)
#pragma unroll
            for (int j = 0; j < 8; j++) acc[i][j] = 0.0f;
        for (int k0 = 0; k0 < K; k0 += 16) {
            for (int it = 0; it < 8; it++) {
                int idx = tid + it * 256;
                int rr = idx >> 4, kk = idx & 15;
                As[kk * 132 + rr] =
                    __bfloat162float(Ah[(size_t)(mb + rr) * K + k0 + kk]) +
                    __bfloat162float(Al[(size_t)(mb + rr) * K + k0 + kk]);
                Bs[kk * 132 + rr] =
                    __bfloat162float(Bh[(size_t)(nb + rr) * K + k0 + kk]) +
                    __bfloat162float(Bl[(size_t)(nb + rr) * K + k0 + kk]);
            }
            __syncthreads();
#pragma unroll
            for (int k = 0; k < 16; k++) {
                float a[8], bb[8];
#pragma unroll
                for (int i = 0; i < 8; i++) a[i] = As[k * 132 + ty * 8 + i];
#pragma unroll
                for (int j = 0; j < 8; j++) bb[j] = Bs[k * 132 + tx * 8 + j];
#pragma unroll
                for (int i = 0; i < 8; i++)
#pragma unroll
                    for (int j = 0; j < 8; j++) acc[i][j] = fmaf(a[i], bb[j], acc[i][j]);
            }
            __syncthreads();
        }
#pragma unroll
        for (int i = 0; i < 8; i++) {
            int row = mb + ty * 8 + i;
#pragma unroll
            for (int j = 0; j < 8; j++) {
                int col = nb + tx * 8 + j;
                float v = acc[i][j];
                if (EPI == 0) {
                    Cf[(size_t)row * N + col] = v;
                } else if (EPI == 1) {
                    v = fmaxf(v + bias0[col], 0.0f);
                    __nv_bfloat16 h = __float2bfloat16(v);
                    Ch[(size_t)row * N + col] = h;
                    Cl[(size_t)row * N + col] = __float2bfloat16(v - __bfloat162float(h));
                } else {
                    int mat = col >> 10, lc = col & 1023;
                    const float* bs = (mat == 0) ? bias0 : (mat == 1) ? bias1 : bias2;
                    __nv_bfloat16* Dd = (mat == 0) ? D0 : (mat == 1) ? D1 : D2;
                    float vv = v + bs[lc];
                    int h_ = lc >> 6, d = lc & 63;
                    int b_ = row >> 11, s_ = row & (SS - 1);
                    Dd[(((size_t)b_ * HH + h_) * SS + s_) * HD + d] = __float2bfloat16(vv);
                }
            }
        }
        __syncthreads();
    }
#endif
}

// ---------------------------------------------------------------------------
// Pipelined tcgen05 flash attention (unchanged from R11; proven)
// ---------------------------------------------------------------------------
constexpr int FL_Q  = 0;
constexpr int FL_K  = 16384;
constexpr int FL_VT = 65536;
constexpr int FL_P  = 114688;
constexpr int FL_MS = 147456;
constexpr int FL_CT = 155648;
constexpr int FL_SMEM = FL_CT + 64 + 1024 + 1024;
constexpr int NKB = SS / 128;

__global__ __launch_bounds__(256, 1) void flash_tc_kernel(
    const __nv_bfloat16* __restrict__ qg, const __nv_bfloat16* __restrict__ kg,
    const __nv_bfloat16* __restrict__ vt, const int* __restrict__ mask,
    __nv_bfloat16* __restrict__ outh, __nv_bfloat16* __restrict__ outl)
{
    extern __shared__ char dsmem[];
    uintptr_t pb = ((uintptr_t)dsmem + 1023) & ~(uintptr_t)1023;
    char* buf = (char*)pb;
    const int tid = threadIdx.x;
    const int wid = tid >> 5;
    const int lane = tid & 31;
    const int bh = blockIdx.y;
    const int b_ = bh >> 4;
    const int h_ = bh & (HH - 1);
    const int q0 = blockIdx.x * 128;

#if HAS_TCGEN05
    const int sp = wid & 3;
    const int chf = wid >> 2;
    const uint32_t sbuf = smem_u32(buf);
    const uint32_t ctrl = sbuf + FL_CT;
    int* msk_s = (int*)(buf + FL_MS);
    float* lpart = (float*)(buf + FL_CT + 64);

    if (wid == 0) TCGEN05_ALLOC(ctrl, 512);
    if (tid == 0) { MBARRIER_INIT(ctrl + 8, 1); MBARRIER_INIT(ctrl + 16, 1); }
    __syncthreads();
    uint32_t tmem;
    asm volatile("ld.shared.b32 %0, [%1];" : "=r"(tmem) : "r"(ctrl));

    auto load_kv = [&](int kb, int st) {
        const uint32_t sbK = sbuf + FL_K + (uint32_t)st * 16384;
        const uint32_t sbV = sbuf + FL_VT + (uint32_t)st * 16384;
#pragma unroll
        for (int j = 0; j < 4; j++) {
            int u = tid + j * 256;
            int r = u >> 3, g = u & 7;
            CP_ASYNC16(sbK + swz128((uint32_t)(r * 128 + g * 16)),
                       kg + ((size_t)(bh * SS + kb * 128 + r)) * HD + g * 8);
        }
#pragma unroll
        for (int j = 0; j < 4; j++) {
            int u = tid + j * 256;
            int d = u >> 4, g = u & 15;
            int key0 = g * 8;
            uint32_t o = (uint32_t)(((key0 >> 6) * 8 + (d >> 3)) * 1024 + (d & 7) * 128 + (key0 & 63) * 2);
            CP_ASYNC16(sbV + swz128(o),
                       vt + ((size_t)(bh * HD + d)) * SS + kb * 128 + key0);
        }
    };

#pragma unroll
    for (int j = 0; j < 4; j++) {
        int u = tid + j * 256;
        int r = u >> 3, g = u & 7;
        CP_ASYNC16(sbuf + FL_Q + swz128((uint32_t)(r * 128 + g * 16)),
                   qg + ((size_t)(bh * SS + q0 + r)) * HD + g * 8);
    }
#pragma unroll
    for (int j = 0; j < 2; j++)
        CP_ASYNC16(sbuf + FL_MS + tid * 16 + j * 4096,
                   mask + b_ * SS + tid * 4 + j * 1024);
    load_kv(0, 0);
    CP_COMMIT();
    load_kv(1, 1);
    CP_COMMIT();

    const uint64_t dQ = make_desc_sw128(sbuf + FL_Q);
    const uint64_t dP = make_desc_sw128(sbuf + FL_P);
    const int pOff[8] = {0, 2, 4, 6, 1024, 1026, 1028, 1030};
    const int vOff[8] = {0, 2, 4, 6, 512, 514, 516, 518};

    CP_WAIT(1);
    __syncthreads();
    FENCE_ASYNC_SHARED();
    if (wid == 0 && elect_one_pred()) {
        uint64_t dK = make_desc_sw128(sbuf + FL_K);
#pragma unroll
        for (int s = 0; s < 4; s++)
            mma_bf16_ss(tmem, dQ + s * 2, dK + s * 2, GEMM_IDESC, s != 0);
        TCGEN05_COMMIT(ctrl + 8);
    }

    float lsum = 0.0f;
    int phS = 0, phO = 0;
    const int r = sp * 32 + lane;

    for (int k = 0; k < NKB; k++) {
        const int st = k % 3;
        const uint32_t sbase = (uint32_t)(k & 1) * 128;

        MBARRIER_WAIT_PARITY(ctrl + 8, phS);
        phS ^= 1;
        TCGEN05_FENCE_AFTER();

        uint32_t ppk[32];
#pragma unroll
        for (int h2 = 0; h2 < 2; h2++) {
            uint32_t sr[32];
            TCGEN05_LD_X32(sr, tmem + sbase + chf * 64 + h2 * 32);
            TCGEN05_WAIT_LD();
            const int cbase = k * 128 + chf * 64 + h2 * 32;
#pragma unroll
            for (int j = 0; j < 16; j++) {
                float p0 = msk_s[cbase + 2 * j]     ? __expf(__uint_as_float(sr[2 * j])     * 0.125f) : 0.0f;
                float p1 = msk_s[cbase + 2 * j + 1] ? __expf(__uint_as_float(sr[2 * j + 1]) * 0.125f) : 0.0f;
                __nv_bfloat16 bp0 = __float2bfloat16(p0), bp1 = __float2bfloat16(p1);
                ppk[h2 * 16 + j] = pack_bf2(bp0, bp1);
                lsum += __bfloat162float(bp0) + __bfloat162float(bp1);
            }
        }

        if (k > 0) { MBARRIER_WAIT_PARITY(ctrl + 16, phO); phO ^= 1; }
        if (k + 2 < NKB) { load_kv(k + 2, (k + 2) % 3); CP_COMMIT(); }

#pragma unroll
        for (int h2 = 0; h2 < 2; h2++) {
            uint32_t pbo = (uint32_t)((chf * 16 + (r >> 3)) * 1024 + (r & 7) * 128 + h2 * 64);
#pragma unroll
            for (int j = 0; j < 4; j++)
                *(uint4*)(buf + FL_P + swz128(pbo + j * 16)) =
                    make_uint4(ppk[h2 * 16 + 4 * j], ppk[h2 * 16 + 4 * j + 1],
                               ppk[h2 * 16 + 4 * j + 2], ppk[h2 * 16 + 4 * j + 3]);
        }
        TCGEN05_FENCE_BEFORE();
        FENCE_ASYNC_SHARED();
        __syncthreads();

        if (wid == 0 && elect_one_pred()) {
            uint64_t dVT = make_desc_sw128(sbuf + FL_VT + (uint32_t)st * 16384);
#pragma unroll
            for (int s = 0; s < 8; s++)
                mma_bf16_ss(tmem + 256, dP + pOff[s], dVT + vOff[s], IDESC_N64,
                            !(k == 0 && s == 0));
            TCGEN05_COMMIT(ctrl + 16);
        }

        if (k + 1 < NKB) {
            if (k + 2 < NKB) CP_WAIT(1);
            else             CP_WAIT(0);
            __syncthreads();
            FENCE_ASYNC_SHARED();
            if (wid == 0 && elect_one_pred()) {
                uint64_t dK = make_desc_sw128(sbuf + FL_K + (uint32_t)((k + 1) % 3) * 16384);
                uint32_t dst = tmem + ((k + 1) & 1) * 128;
#pragma unroll
                for (int s = 0; s < 4; s++)
                    mma_bf16_ss(dst, dQ + s * 2, dK + s * 2, GEMM_IDESC, s != 0);
                TCGEN05_COMMIT(ctrl + 8);
            }
        }
    }

    MBARRIER_WAIT_PARITY(ctrl + 16, phO);
    TCGEN05_FENCE_AFTER();
    lpart[chf * 128 + r] = lsum;
    __syncthreads();

    if (wid < 4) {
        uint32_t orr[64];
        TCGEN05_LD_X32(orr, tmem + 256);
        TCGEN05_LD_X32(orr + 32, tmem + 288);
        TCGEN05_WAIT_LD();
        TCGEN05_FENCE_BEFORE();
        float inv = 1.0f / (lpart[r] + lpart[128 + r]);
        size_t base = ((size_t)(b_ * SS + q0 + r)) * DD + h_ * HD;
#pragma unroll
        for (int j8 = 0; j8 < 8; j8++) {
            uint32_t hw[4], lw[4];
#pragma unroll
            for (int q = 0; q < 4; q++) {
                int j = j8 * 8 + q * 2;
                float v0 = __uint_as_float(orr[j])     * inv;
                float v1 = __uint_as_float(orr[j + 1]) * inv;
                __nv_bfloat16 h0 = __float2bfloat16(v0), h1 = __float2bfloat16(v1);
                hw[q] = pack_bf2(h0, h1);
                lw[q] = pack_bf2(__float2bfloat16(v0 - __bfloat162float(h0)),
                                 __float2bfloat16(v1 - __bfloat162float(h1)));
            }
            *(uint4*)(outh + base + j8 * 8) = make_uint4(hw[0], hw[1], hw[2], hw[3]);
            *(uint4*)(outl + base + j8 * 8) = make_uint4(lw[0], lw[1], lw[2], lw[3]);
        }
    }
    __syncthreads();
    if (tid == 0) { MBARRIER_INVAL(ctrl + 8); MBARRIER_INVAL(ctrl + 16); }
    __syncthreads();
    if (wid == 0) TCGEN05_DEALLOC(tmem, 512);
#else
    if (tid < 128) {
        int rr = q0 + tid;
        float qr[64], o[64], l = 0.0f;
        for (int d = 0; d < 64; d++) {
            qr[d] = __bfloat162float(qg[((size_t)(bh * SS + rr)) * HD + d]);
            o[d] = 0.0f;
        }
        for (int key = 0; key < SS; key++) {
            if (!mask[b_ * SS + key]) continue;
            float s = 0.0f;
            const __nv_bfloat16* kp = kg + ((size_t)(bh * SS + key)) * HD;
            for (int d = 0; d < 64; d++) s += qr[d] * __bfloat162float(kp[d]);
            float pw = __expf(s * 0.125f);
            l += pw;
            for (int d = 0; d < 64; d++)
                o[d] += pw * __bfloat162float(vt[((size_t)(bh * HD + d)) * SS + key]);
        }
        float inv = 1.0f / l;
        for (int d = 0; d < 64; d++) {
            float v = o[d] * inv;
            __nv_bfloat16 h = __float2bfloat16(v);
            size_t idx = ((size_t)(bh * SS + rr)) * HD;  // token layout below
            (void)idx;
            size_t od = ((size_t)(b_ * SS + rr)) * DD + h_ * HD + d;
            outh[od] = h;
            outl[od] = __float2bfloat16(v - __bfloat162float(h));
        }
    }
#endif
}

// ---------------- residual + bias + LN ----------------
template <bool SPLIT>
__global__ __launch_bounds__(256) void add_ln_kernel(
    const float* __restrict__ a, const float* __restrict__ b,
    const float* __restrict__ bias,
    const float* __restrict__ g, const float* __restrict__ be,
    float* __restrict__ out,
    __nv_bfloat16* __restrict__ oh, __nv_bfloat16* __restrict__ ol)
{
    __shared__ float sh[10];
    const int row = blockIdx.x;
    const int tid = threadIdx.x;
    const int wid = tid >> 5, lane = tid & 31;
    const size_t base = (size_t)row * DD + tid * 4;

    float4 av = *(const float4*)(a + base);
    float4 bv = *(const float4*)(b + base);
    float4 cv = *(const float4*)(bias + tid * 4);
    float4 t = make_float4(av.x + bv.x + cv.x, av.y + bv.y + cv.y,
                           av.z + bv.z + cv.z, av.w + bv.w + cv.w);
    float s = t.x + t.y + t.z + t.w;
#pragma unroll
    for (int off = 16; off >= 1; off >>= 1) s += __shfl_xor_sync(0xffffffffu, s, off);
    if (lane == 0) sh[wid] = s;
    __syncthreads();
    if (tid == 0) {
        float t2 = 0.f;
#pragma unroll
        for (int w = 0; w < 8; w++) t2 += sh[w];
        sh[8] = t2 * (1.0f / 1024.0f);
    }
    __syncthreads();
    float mu = sh[8];
    float dx = t.x - mu, dy = t.y - mu, dz = t.z - mu, dw = t.w - mu;
    float sq = dx * dx + dy * dy + dz * dz + dw * dw;
#pragma unroll
    for (int off = 16; off >= 1; off >>= 1) sq += __shfl_xor_sync(0xffffffffu, sq, off);
    if (lane == 0) sh[wid] = sq;
    __syncthreads();
    if (tid == 0) {
        float t2 = 0.f;
#pragma unroll
        for (int w = 0; w < 8; w++) t2 += sh[w];
        sh[9] = rsqrtf(t2 * (1.0f / 1024.0f) + 1e-5f);
    }
    __syncthreads();
    float inv = sh[9];
    float4 gv = *(const float4*)(g + tid * 4);
    float4 bev = *(const float4*)(be + tid * 4);
    float4 r = make_float4(dx * inv * gv.x + bev.x, dy * inv * gv.y + bev.y,
                           dz * inv * gv.z + bev.z, dw * inv * gv.w + bev.w);
    *(float4*)(out + base) = r;
    if (SPLIT) {
        __nv_bfloat16 h0 = __float2bfloat16(r.x), h1 = __float2bfloat16(r.y);
        __nv_bfloat16 h2 = __float2bfloat16(r.z), h3 = __float2bfloat16(r.w);
        *(uint2*)(oh + base) = make_uint2(pack_bf2(h0, h1), pack_bf2(h2, h3));
        *(uint2*)(ol + base) = make_uint2(
            pack_bf2(__float2bfloat16(r.x - __bfloat162float(h0)),
                     __float2bfloat16(r.y - __bfloat162float(h1))),
            pack_bf2(__float2bfloat16(r.z - __bfloat162float(h2)),
                     __float2bfloat16(r.w - __bfloat162float(h3))));
    }
}

// ---------------------------------------------------------------------------
extern "C" void kernel_launch(void* const* d_in, const int* in_sizes, int n_in,
                              void* d_out, int out_size)
{
    const float* x   = (const float*)d_in[0];
    const int*   msk = (const int*)d_in[1];
    const float* Wq  = (const float*)d_in[2];
    const float* bq  = (const float*)d_in[3];
    const float* Wk  = (const float*)d_in[4];
    const float* bk  = (const float*)d_in[5];
    const float* Wv  = (const float*)d_in[6];
    const float* bv  = (const float*)d_in[7];
    const float* Wo  = (const float*)d_in[8];
    const float* bo  = (const float*)d_in[9];
    const float* W1  = (const float*)d_in[10];
    const float* b1  = (const float*)d_in[11];
    const float* W2  = (const float*)d_in[12];
    const float* b2  = (const float*)d_in[13];
    const float* g1  = (const float*)d_in[14];
    const float* be1 = (const float*)d_in[15];
    const float* g2  = (const float*)d_in[16];
    const float* be2 = (const float*)d_in[17];
    float* out = (float*)d_out;

    __nv_bfloat16 *xh, *xl, *qh, *kh, *vh, *vt, *oh, *ol, *hb, *hl, *fh, *fl, *wh, *wl;
    float *f32a, *f32b, *f32c;
    cudaGetSymbolAddress((void**)&xh, g_xh);
    cudaGetSymbolAddress((void**)&xl, g_xl);
    cudaGetSymbolAddress((void**)&qh, g_qh);
    cudaGetSymbolAddress((void**)&kh, g_kh);
    cudaGetSymbolAddress((void**)&vh, g_vh);
    cudaGetSymbolAddress((void**)&vt, g_vt);
    cudaGetSymbolAddress((void**)&oh, g_oh);
    cudaGetSymbolAddress((void**)&ol, g_ol);
    cudaGetSymbolAddress((void**)&hb, g_hb);
    cudaGetSymbolAddress((void**)&hl, g_hl);
    cudaGetSymbolAddress((void**)&fh, g_fh);
    cudaGetSymbolAddress((void**)&fl, g_fl);
    cudaGetSymbolAddress((void**)&wh, g_wh);
    cudaGetSymbolAddress((void**)&wl, g_wl);
    cudaGetSymbolAddress((void**)&f32a, g_f32a);
    cudaGetSymbolAddress((void**)&f32b, g_f32b);
    cudaGetSymbolAddress((void**)&f32c, g_f32c);

    cudaFuncSetAttribute(gemm_bf<0>, cudaFuncAttributeMaxDynamicSharedMemorySize, GEMM_SMEM_BYTES);
    cudaFuncSetAttribute(gemm_bf<1>, cudaFuncAttributeMaxDynamicSharedMemorySize, GEMM_SMEM_BYTES);
    cudaFuncSetAttribute(gemm_bf<2>, cudaFuncAttributeMaxDynamicSharedMemorySize, GEMM_SMEM_BYTES);
    cudaFuncSetAttribute(flash_tc_kernel, cudaFuncAttributeMaxDynamicSharedMemorySize, FL_SMEM);

    dim3 blk(256);
    dim3 pw(32, 8);

    // x -> bf16 hi/lo
    split_kernel<<<(size_t)MM * DD / 1024, blk>>>(x, xh, xl);

    // weights -> transposed bf16 hi/lo
    prep_w_kernel<<<dim3(DD / 32, DD / 32), pw>>>(Wq, wh + WQ_OFF, wl + WQ_OFF, DD, DD);
    prep_w_kernel<<<dim3(DD / 32, DD / 32), pw>>>(Wk, wh + WK_OFF, wl + WK_OFF, DD, DD);
    prep_w_kernel<<<dim3(DD / 32, DD / 32), pw>>>(Wv, wh + WV_OFF, wl + WV_OFF, DD, DD);
    prep_w_kernel<<<dim3(DD / 32, DD / 32), pw>>>(Wo, wh + WO_OFF, wl + WO_OFF, DD, DD);
    prep_w_kernel<<<dim3(FF / 32, DD / 32), pw>>>(W1, wh + W1_OFF, wl + W1_OFF, DD, FF);
    prep_w_kernel<<<dim3(DD / 32, FF / 32), pw>>>(W2, wh + W2_OFF, wl + W2_OFF, FF, DD);

    // QKV combined (N=3072): 256x256 tiles
    gemm_bf<2><<<dim3(12, 32), blk, GEMM_SMEM_BYTES>>>(
        xh, xl, wh + WQ_OFF, wl + WQ_OFF,
        nullptr, nullptr, nullptr, qh, kh, vh, bq, bk, bv, MM, 3 * DD, DD);

    // V -> V^T
    transpose_v_kernel<<<dim3(SS / 64, BB * HH), blk>>>(vh, vt);

    // pipelined flash attention
    flash_tc_kernel<<<dim3(SS / 128, BB * HH), blk, FL_SMEM>>>(qh, kh, vt, msk, oh, ol);

    // O projection (fp32 out, bias folded into LN)
    gemm_bf<0><<<dim3(4, 32), blk, GEMM_SMEM_BYTES>>>(
        oh, ol, wh + WO_OFF, wl + WO_OFF,
        f32a, nullptr, nullptr, nullptr, nullptr, nullptr, nullptr, nullptr, nullptr,
        MM, DD, DD);

    // h = LN(x + o + bo): fp32 + bf16 split
    add_ln_kernel<true><<<MM, blk>>>(x, f32a, bo, g1, be1, f32b, hb, hl);

    // FFN1: relu(h W1 + b1) -> bf16 hi/lo
    gemm_bf<1><<<dim3(16, 32), blk, GEMM_SMEM_BYTES>>>(
        hb, hl, wh + W1_OFF, wl + W1_OFF,
        nullptr, fh, fl, nullptr, nullptr, nullptr, b1, nullptr, nullptr, MM, FF, DD);

    // FFN2 (fp32 out)
    gemm_bf<0><<<dim3(4, 32), blk, GEMM_SMEM_BYTES>>>(
        fh, fl, wh + W2_OFF, wl + W2_OFF,
        f32c, nullptr, nullptr, nullptr, nullptr, nullptr, nullptr, nullptr, nullptr,
        MM, DD, FF);

    // out = LN(h + ffn + b2)
    add_ln_kernel<false><<<MM, blk>>>(f32b, f32c, b2, g2, be2, out, nullptr, nullptr);
}

// round 13
// speedup vs baseline: 1.0984x; 1.0984x over previous
#include <cuda_runtime.h>
#include <cuda_bf16.h>
#include <math.h>
#include <stdint.h>

constexpr int BB = 4;
constexpr int SS = 2048;
constexpr int DD = 1024;
constexpr int HH = 16;
constexpr int HD = 64;
constexpr int FF = 4096;
constexpr int MM = BB * SS;

#if defined(__CUDA_ARCH_FEAT_SM103_ALL) || defined(__CUDA_ARCH_FEAT_SM100_ALL)
#define HAS_TCGEN05 1
#else
#define HAS_TCGEN05 0
#endif

// ---------------- device scratch ----------------
__device__ __nv_bfloat16 g_xh[(size_t)MM * DD];
__device__ __nv_bfloat16 g_xl[(size_t)MM * DD];
__device__ __nv_bfloat16 g_qh[(size_t)MM * DD];
__device__ __nv_bfloat16 g_kh[(size_t)MM * DD];
__device__ __nv_bfloat16 g_vh[(size_t)MM * DD];
__device__ __nv_bfloat16 g_vt[(size_t)MM * DD];   // V transposed [B,H,HD,SS]
__device__ __nv_bfloat16 g_oh[(size_t)MM * DD];
__device__ __nv_bfloat16 g_ol[(size_t)MM * DD];
__device__ __nv_bfloat16 g_hb[(size_t)MM * DD];
__device__ __nv_bfloat16 g_hl[(size_t)MM * DD];
__device__ __nv_bfloat16 g_fh[(size_t)MM * FF];
__device__ __nv_bfloat16 g_fl[(size_t)MM * FF];
__device__ float g_f32a[(size_t)MM * DD];
__device__ float g_f32b[(size_t)MM * DD];
__device__ float g_f32c[(size_t)MM * DD];

constexpr size_t WQ_OFF = 0;
constexpr size_t WK_OFF = 1048576;
constexpr size_t WV_OFF = 2097152;
constexpr size_t WO_OFF = 3145728;
constexpr size_t W1_OFF = 4194304;
constexpr size_t W2_OFF = 8388608;
constexpr size_t WTOT   = 12582912;
__device__ __nv_bfloat16 g_wh[WTOT];
__device__ __nv_bfloat16 g_wl[WTOT];

// ---------------- helpers ----------------
__device__ __forceinline__ uint32_t smem_u32(const void* p) {
    uint32_t a;
    asm("{ .reg .u64 t; cvta.to.shared.u64 t, %1; cvt.u32.u64 %0, t; }" : "=r"(a) : "l"(p));
    return a;
}
__device__ __forceinline__ uint32_t swz128(uint32_t off) { return off ^ ((off >> 3) & 0x70); }
__device__ __forceinline__ uint32_t pack_bf2(__nv_bfloat16 a, __nv_bfloat16 b) {
    __nv_bfloat162 t; t.x = a; t.y = b; return *(uint32_t*)&t;
}
#define CP_ASYNC16(saddr, gptr) \
    asm volatile("cp.async.cg.shared.global [%0], [%1], 16;" \
        :: "r"((uint32_t)(saddr)), "l"(gptr) : "memory")
#define CP_COMMIT() asm volatile("cp.async.commit_group;" ::: "memory")
#define CP_WAIT(n)  asm volatile("cp.async.wait_group %0;" :: "n"(n) : "memory")

#if HAS_TCGEN05
__device__ __forceinline__ uint32_t elect_one_pred() {
    uint32_t pred;
    asm volatile("{\n\t.reg .pred p;\n\telect.sync _|p, 0xFFFFFFFF;\n\tselp.b32 %0, 1, 0, p;\n\t}" : "=r"(pred));
    return pred;
}
#define TCGEN05_ALLOC(smem_addr, nCols) \
    asm volatile("tcgen05.alloc.cta_group::1.sync.aligned.shared::cta.b32 [%0], %1;" \
        :: "r"((uint32_t)(smem_addr)), "r"((uint32_t)(nCols)) : "memory")
#define TCGEN05_DEALLOC(tmem_addr, nCols) \
    asm volatile("tcgen05.dealloc.cta_group::1.sync.aligned.b32 %0, %1;" \
        :: "r"(tmem_addr), "r"((uint32_t)(nCols)))
#define TCGEN05_COMMIT(mbar) \
    asm volatile("tcgen05.commit.cta_group::1.mbarrier::arrive::one.shared::cluster.b64 [%0];" \
        :: "r"((uint32_t)(mbar)) : "memory")
#define TCGEN05_WAIT_LD()  asm volatile("tcgen05.wait::ld.sync.aligned;" ::: "memory")
#define TCGEN05_FENCE_BEFORE() asm volatile("tcgen05.fence::before_thread_sync;" ::: "memory")
#define TCGEN05_FENCE_AFTER()  asm volatile("tcgen05.fence::after_thread_sync;" ::: "memory")
#define FENCE_ASYNC_SHARED() asm volatile("fence.proxy.async.shared::cta;" ::: "memory")
#define MBARRIER_INIT(mbar, cnt) \
    asm volatile("mbarrier.init.shared.b64 [%0], %1;" :: "r"((uint32_t)(mbar)), "r"((uint32_t)(cnt)) : "memory")
#define MBARRIER_INVAL(mbar) \
    asm volatile("mbarrier.inval.shared.b64 [%0];" :: "r"((uint32_t)(mbar)) : "memory")
#define MBARRIER_WAIT_PARITY(mbar, parity) do {                                    \
    uint32_t _mb = (uint32_t)(mbar);                                               \
    uint32_t _pa = (uint32_t)(parity);                                             \
    uint32_t _done;                                                                \
    asm volatile(                                                                  \
        "{\n\t.reg .pred p;\n\t"                                                   \
        "mbarrier.try_wait.parity.acquire.cta.shared::cta.b64 p, [%1], %2;\n\t"    \
        "selp.b32 %0, 1, 0, p;\n\t}"                                               \
        : "=r"(_done) : "r"(_mb), "r"(_pa) : "memory");                            \
    if (!_done) {                                                                  \
        asm volatile(                                                              \
            "{\n\t.reg .pred P1;\n\t"                                              \
            "WL_%=:\n\t"                                                           \
            "mbarrier.try_wait.parity.acquire.cta.shared::cta.b64 P1, [%0], %1, 0x989680;\n\t" \
            "@P1 bra.uni WD_%=;\n\t"                                               \
            "bra.uni WL_%=;\n\t"                                                   \
            "WD_%=:\n\t}"                                                          \
            :: "r"(_mb), "r"(_pa) : "memory");                                     \
    }                                                                              \
} while (0)
#define TCGEN05_LD_X32(r, addr) \
    asm volatile( \
        "tcgen05.ld.sync.aligned.32x32b.x32.b32 " \
        "{%0, %1, %2, %3, %4, %5, %6, %7, " \
        " %8, %9, %10, %11, %12, %13, %14, %15, " \
        " %16, %17, %18, %19, %20, %21, %22, %23, " \
        " %24, %25, %26, %27, %28, %29, %30, %31}, [%32];" \
        : "=r"((r)[0]),  "=r"((r)[1]),  "=r"((r)[2]),  "=r"((r)[3]), \
          "=r"((r)[4]),  "=r"((r)[5]),  "=r"((r)[6]),  "=r"((r)[7]), \
          "=r"((r)[8]),  "=r"((r)[9]),  "=r"((r)[10]), "=r"((r)[11]), \
          "=r"((r)[12]), "=r"((r)[13]), "=r"((r)[14]), "=r"((r)[15]), \
          "=r"((r)[16]), "=r"((r)[17]), "=r"((r)[18]), "=r"((r)[19]), \
          "=r"((r)[20]), "=r"((r)[21]), "=r"((r)[22]), "=r"((r)[23]), \
          "=r"((r)[24]), "=r"((r)[25]), "=r"((r)[26]), "=r"((r)[27]), \
          "=r"((r)[28]), "=r"((r)[29]), "=r"((r)[30]), "=r"((r)[31]) \
        : "r"(addr))

__device__ __forceinline__ uint64_t make_desc_sw128(uint32_t addr) {
    constexpr uint64_t BASE =
        (uint64_t(2) << 61) | (uint64_t(1) << 46) | (uint64_t(64) << 32) | (uint64_t(1) << 16);
    return BASE | ((uint64_t)(addr >> 4) & 0x3FFF);
}
__device__ __forceinline__ void mma_bf16_ss(uint32_t d, uint64_t ad, uint64_t bd,
                                            uint32_t idesc, bool acc) {
    uint32_t en = acc ? 1u : 0u;
    asm volatile(
        "{\n\t.reg .pred p;\n\t"
        "setp.ne.u32 p, %5, 0;\n\t"
        "tcgen05.mma.cta_group::1.kind::f16 [%0], %1, %2, %3, {%4, %4, %4, %4}, p;\n\t}"
        :: "r"(d), "l"(ad), "l"(bd), "r"(idesc), "r"(0u), "r"(en) : "memory");
}
#endif

constexpr uint32_t GEMM_IDESC =
    (1u << 4) | (1u << 7) | (1u << 10) | ((128 / 8) << 17) | ((128 / 16) << 24);
constexpr uint32_t IDESC_N64 =
    (1u << 4) | (1u << 7) | (1u << 10) | ((64 / 8) << 17) | ((128 / 16) << 24);

// ---------------- weight prep ----------------
__global__ void prep_w_kernel(const float* __restrict__ W,
                              __nv_bfloat16* __restrict__ Bh,
                              __nv_bfloat16* __restrict__ Bl, int K, int N)
{
    __shared__ float t[32][33];
    const int n0 = blockIdx.x * 32, k0 = blockIdx.y * 32;
#pragma unroll
    for (int i = 0; i < 4; i++)
        t[threadIdx.y + i * 8][threadIdx.x] =
            W[(size_t)(k0 + threadIdx.y + i * 8) * N + n0 + threadIdx.x];
    __syncthreads();
#pragma unroll
    for (int i = 0; i < 4; i++) {
        int n = threadIdx.y + i * 8;
        float v = t[threadIdx.x][n];
        __nv_bfloat16 h = __float2bfloat16(v);
        size_t idx = (size_t)(n0 + n) * K + k0 + threadIdx.x;
        Bh[idx] = h;
        Bl[idx] = __float2bfloat16(v - __bfloat162float(h));
    }
}

// fp32 -> bf16 hi/lo split
__global__ __launch_bounds__(256) void split_kernel(
    const float* __restrict__ in,
    __nv_bfloat16* __restrict__ oh, __nv_bfloat16* __restrict__ ol)
{
    size_t i = ((size_t)blockIdx.x * 256 + threadIdx.x) * 4;
    float4 v = *(const float4*)(in + i);
    __nv_bfloat16 h0 = __float2bfloat16(v.x), h1 = __float2bfloat16(v.y);
    __nv_bfloat16 h2 = __float2bfloat16(v.z), h3 = __float2bfloat16(v.w);
    *(uint2*)(oh + i) = make_uint2(pack_bf2(h0, h1), pack_bf2(h2, h3));
    *(uint2*)(ol + i) = make_uint2(
        pack_bf2(__float2bfloat16(v.x - __bfloat162float(h0)),
                 __float2bfloat16(v.y - __bfloat162float(h1))),
        pack_bf2(__float2bfloat16(v.z - __bfloat162float(h2)),
                 __float2bfloat16(v.w - __bfloat162float(h3))));
}

// V transpose: vh [BH][SS][HD] -> vt [BH][HD][SS]
__global__ __launch_bounds__(256) void transpose_v_kernel(
    const __nv_bfloat16* __restrict__ vh, __nv_bfloat16* __restrict__ vt)
{
    __shared__ __nv_bfloat16 t[64][72];
    const int bh = blockIdx.y;
    const int s0 = blockIdx.x * 64;
    const int r = threadIdx.x >> 2;
    const int c = (threadIdx.x & 3) * 16;
    const __nv_bfloat16* src = vh + ((size_t)(bh * SS + s0 + r)) * HD + c;
    *(uint4*)(&t[r][c])     = *(const uint4*)(src);
    *(uint4*)(&t[r][c + 8]) = *(const uint4*)(src + 8);
    __syncthreads();
    __nv_bfloat16* dst = vt + ((size_t)(bh * HD + r)) * SS + s0 + c;
    __nv_bfloat16 tmp[16];
#pragma unroll
    for (int j = 0; j < 16; j++) tmp[j] = t[c + j][r];
    *(uint4*)(dst)     = *(uint4*)(tmp);
    *(uint4*)(dst + 8) = *(uint4*)(tmp + 8);
}

// ---------------------------------------------------------------------------
// GEMM (R11 proven config): 256x128 CTA tile, SW128, 2-stage cp.async.
// Stage (96KB): Ah 32K (256 rows) | Al 32K | Bh 16K | Bl 16K
// ---------------------------------------------------------------------------
constexpr int GEMM_STAGE = 98304;
constexpr int GEMM_SMEM_BYTES = 2 * GEMM_STAGE + 1024;

template <int EPI>
__global__ __launch_bounds__(256, 1) void gemm_bf(
    const __nv_bfloat16* __restrict__ Ah, const __nv_bfloat16* __restrict__ Al,
    const __nv_bfloat16* __restrict__ Bh, const __nv_bfloat16* __restrict__ Bl,
    float* __restrict__ Cf, __nv_bfloat16* __restrict__ Ch, __nv_bfloat16* __restrict__ Cl,
    __nv_bfloat16* __restrict__ D0, __nv_bfloat16* __restrict__ D1, __nv_bfloat16* __restrict__ D2,
    const float* __restrict__ bias0, const float* __restrict__ bias1, const float* __restrict__ bias2,
    int M, int N, int K)
{
    extern __shared__ char dsmem[];
    uintptr_t p = ((uintptr_t)dsmem + 1023) & ~(uintptr_t)1023;
    char* buf = (char*)p;
    const int tid = threadIdx.x;
    const int wid = tid >> 5;
    const int lane = tid & 31;
    const int m0 = blockIdx.y << 8;
    const int n0 = blockIdx.x << 7;

#if HAS_TCGEN05
    __shared__ alignas(16) unsigned long long ctrlq[4];
    const uint32_t sbuf = smem_u32(buf);
    const uint32_t ctrl = smem_u32(ctrlq);

    if (wid == 0) TCGEN05_ALLOC(ctrl, 256);
    if (tid == 0) {
        MBARRIER_INIT(ctrl + 8, 1);
        MBARRIER_INIT(ctrl + 16, 1);
        MBARRIER_INIT(ctrl + 24, 1);
    }
    __syncthreads();
    uint32_t tmem;
    asm volatile("ld.shared.b32 %0, [%1];" : "=r"(tmem) : "r"(ctrl));

    const int NC = K >> 6;

    auto load_chunk = [&](int ck, int st) {
        const uint32_t sb = sbuf + (uint32_t)st * GEMM_STAGE;
        const int k0 = ck << 6;
#pragma unroll
        for (int j = 0; j < 8; j++) {
            int u = tid + j * 256;
            int r = u >> 3, g = u & 7;
            uint32_t so = swz128((uint32_t)(r * 128 + g * 16));
            size_t ao = (size_t)(m0 + r) * K + k0 + g * 8;
            CP_ASYNC16(sb + so,         Ah + ao);
            CP_ASYNC16(sb + 32768 + so, Al + ao);
        }
#pragma unroll
        for (int j = 0; j < 4; j++) {
            int u = tid + j * 256;
            int r = u >> 3, g = u & 7;
            uint32_t so = swz128((uint32_t)(r * 128 + g * 16));
            size_t bo = (size_t)(n0 + r) * K + k0 + g * 8;
            CP_ASYNC16(sb + 65536 + so, Bh + bo);
            CP_ASYNC16(sb + 81920 + so, Bl + bo);
        }
    };

    load_chunk(0, 0);
    CP_COMMIT();
    load_chunk(1, 1);
    CP_COMMIT();

    int ph[2] = {0, 0};

    for (int i = 0; i < NC; i++) {
        const int st = i & 1;
        if (i < NC - 1) CP_WAIT(1);
        else            CP_WAIT(0);
        __syncthreads();
        FENCE_ASYNC_SHARED();

        if (wid == 0 && elect_one_pred()) {
            const uint32_t sb = sbuf + (uint32_t)st * GEMM_STAGE;
            uint64_t dBh = make_desc_sw128(sb + 65536);
            uint64_t dBl = make_desc_sw128(sb + 81920);
#pragma unroll
            for (int mt = 0; mt < 2; mt++) {
                uint64_t dAh = make_desc_sw128(sb + mt * 16384);
                uint64_t dAl = make_desc_sw128(sb + 32768 + mt * 16384);
                uint32_t dst = tmem + mt * 128;
#pragma unroll
                for (int ks = 0; ks < 4; ks++)
                    mma_bf16_ss(dst, dAh + ks * 2, dBh + ks * 2, GEMM_IDESC, !(i == 0 && ks == 0));
#pragma unroll
                for (int ks = 0; ks < 4; ks++)
                    mma_bf16_ss(dst, dAl + ks * 2, dBh + ks * 2, GEMM_IDESC, true);
#pragma unroll
                for (int ks = 0; ks < 4; ks++)
                    mma_bf16_ss(dst, dAh + ks * 2, dBl + ks * 2, GEMM_IDESC, true);
            }
            TCGEN05_COMMIT(ctrl + 8 + st * 8);
        }

        if (i + 2 < NC) {
            MBARRIER_WAIT_PARITY(ctrl + 8 + st * 8, ph[st]);
            ph[st] ^= 1;
            load_chunk(i + 2, st);
            CP_COMMIT();
        }
    }

    if (wid == 0 && elect_one_pred()) TCGEN05_COMMIT(ctrl + 24);
    MBARRIER_WAIT_PARITY(ctrl + 24, 0);
    TCGEN05_FENCE_AFTER();

    {
        const int sp = wid & 3;
        const int chf = wid >> 2;
#pragma unroll
        for (int mt = 0; mt < 2; mt++) {
            uint32_t r[64];
            TCGEN05_LD_X32(r, tmem + mt * 128 + chf * 64);
            TCGEN05_LD_X32(r + 32, tmem + mt * 128 + chf * 64 + 32);
            TCGEN05_WAIT_LD();
            TCGEN05_FENCE_BEFORE();

            const int row = m0 + mt * 128 + sp * 32 + lane;
            const int c0 = n0 + chf * 64;

            if (EPI == 0) {
                float* cp = Cf + (size_t)row * N + c0;
#pragma unroll
                for (int c = 0; c < 16; c++) {
                    float4 v;
                    v.x = __uint_as_float(r[4 * c + 0]);
                    v.y = __uint_as_float(r[4 * c + 1]);
                    v.z = __uint_as_float(r[4 * c + 2]);
                    v.w = __uint_as_float(r[4 * c + 3]);
                    *(float4*)(cp + 4 * c) = v;
                }
            } else if (EPI == 1) {
                size_t base = (size_t)row * N + c0;
#pragma unroll
                for (int j8 = 0; j8 < 8; j8++) {
                    uint32_t hw[4], lw[4];
#pragma unroll
                    for (int q = 0; q < 4; q++) {
                        int j = j8 * 8 + q * 2;
                        float v0 = fmaxf(__uint_as_float(r[j])     + bias0[c0 + j],     0.0f);
                        float v1 = fmaxf(__uint_as_float(r[j + 1]) + bias0[c0 + j + 1], 0.0f);
                        __nv_bfloat16 h0 = __float2bfloat16(v0), h1 = __float2bfloat16(v1);
                        hw[q] = pack_bf2(h0, h1);
                        lw[q] = pack_bf2(__float2bfloat16(v0 - __bfloat162float(h0)),
                                         __float2bfloat16(v1 - __bfloat162float(h1)));
                    }
                    *(uint4*)(Ch + base + j8 * 8) = make_uint4(hw[0], hw[1], hw[2], hw[3]);
                    *(uint4*)(Cl + base + j8 * 8) = make_uint4(lw[0], lw[1], lw[2], lw[3]);
                }
            } else {
                const int mat = c0 >> 10;
                const int lc = c0 & 1023;
                const float* bs = (mat == 0) ? bias0 : (mat == 1) ? bias1 : bias2;
                __nv_bfloat16* Dd = (mat == 0) ? D0 : (mat == 1) ? D1 : D2;
                const int h_ = lc >> 6;
                const int b_ = row >> 11;
                const int s_ = row & (SS - 1);
                size_t base = (((size_t)b_ * HH + h_) * SS + s_) * HD;
#pragma unroll
                for (int j8 = 0; j8 < 8; j8++) {
                    uint32_t hw[4];
#pragma unroll
                    for (int q = 0; q < 4; q++) {
                        int j = j8 * 8 + q * 2;
                        float v0 = __uint_as_float(r[j])     + bs[lc + j];
                        float v1 = __uint_as_float(r[j + 1]) + bs[lc + j + 1];
                        hw[q] = pack_bf2(__float2bfloat16(v0), __float2bfloat16(v1));
                    }
                    *(uint4*)(Dd + base + j8 * 8) = make_uint4(hw[0], hw[1], hw[2], hw[3]);
                }
            }
        }
    }

    __syncthreads();
    if (tid == 0) {
        MBARRIER_INVAL(ctrl + 8);
        MBARRIER_INVAL(ctrl + 16);
        MBARRIER_INVAL(ctrl + 24);
    }
    __syncthreads();
    if (wid == 0) TCGEN05_DEALLOC(tmem, 256);

#else  // FFMA fallback
    float* As = (float*)buf;
    float* Bs = As + 16 * 132;
    const int tx = tid & 15, ty = tid >> 4;
    for (int mt = 0; mt < 2; mt++) {
        const int mb = m0 + mt * 128;
        float acc[8][8];
#pragma unroll
        for (int i = 0; i < 8; i++)
#pragma unroll
            for (int j = 0; j < 8; j++) acc[i][j] = 0.0f;
        for (int k0 = 0; k0 < K; k0 += 16) {
            for (int it = 0; it < 8; it++) {
                int idx = tid + it * 256;
                int rr = idx >> 4, kk = idx & 15;
                As[kk * 132 + rr] =
                    __bfloat162float(Ah[(size_t)(mb + rr) * K + k0 + kk]) +
                    __bfloat162float(Al[(size_t)(mb + rr) * K + k0 + kk]);
                Bs[kk * 132 + rr] =
                    __bfloat162float(Bh[(size_t)(n0 + rr) * K + k0 + kk]) +
                    __bfloat162float(Bl[(size_t)(n0 + rr) * K + k0 + kk]);
            }
            __syncthreads();
#pragma unroll
            for (int k = 0; k < 16; k++) {
                float a[8], bb[8];
#pragma unroll
                for (int i = 0; i < 8; i++) a[i] = As[k * 132 + ty * 8 + i];
#pragma unroll
                for (int j = 0; j < 8; j++) bb[j] = Bs[k * 132 + tx * 8 + j];
#pragma unroll
                for (int i = 0; i < 8; i++)
#pragma unroll
                    for (int j = 0; j < 8; j++) acc[i][j] = fmaf(a[i], bb[j], acc[i][j]);
            }
            __syncthreads();
        }
#pragma unroll
        for (int i = 0; i < 8; i++) {
            int row = mb + ty * 8 + i;
#pragma unroll
            for (int j = 0; j < 8; j++) {
                int col = n0 + tx * 8 + j;
                float v = acc[i][j];
                if (EPI == 0) {
                    Cf[(size_t)row * N + col] = v;
                } else if (EPI == 1) {
                    v = fmaxf(v + bias0[col], 0.0f);
                    __nv_bfloat16 h = __float2bfloat16(v);
                    Ch[(size_t)row * N + col] = h;
                    Cl[(size_t)row * N + col] = __float2bfloat16(v - __bfloat162float(h));
                } else {
                    int mat = col >> 10, lc = col & 1023;
                    const float* bs = (mat == 0) ? bias0 : (mat == 1) ? bias1 : bias2;
                    __nv_bfloat16* Dd = (mat == 0) ? D0 : (mat == 1) ? D1 : D2;
                    float vv = v + bs[lc];
                    int h_ = lc >> 6, d = lc & 63;
                    int b_ = row >> 11, s_ = row & (SS - 1);
                    Dd[(((size_t)b_ * HH + h_) * SS + s_) * HD + d] = __float2bfloat16(vv);
                }
            }
        }
        __syncthreads();
    }
#endif
}

// ---------------------------------------------------------------------------
// Pipelined tcgen05 flash attention (R11 + early-S issue + single LDTM wait)
// ---------------------------------------------------------------------------
constexpr int FL_Q  = 0;
constexpr int FL_K  = 16384;
constexpr int FL_VT = 65536;
constexpr int FL_P  = 114688;
constexpr int FL_MS = 147456;
constexpr int FL_CT = 155648;
constexpr int FL_SMEM = FL_CT + 64 + 1024 + 1024;
constexpr int NKB = SS / 128;

__global__ __launch_bounds__(256, 1) void flash_tc_kernel(
    const __nv_bfloat16* __restrict__ qg, const __nv_bfloat16* __restrict__ kg,
    const __nv_bfloat16* __restrict__ vt, const int* __restrict__ mask,
    __nv_bfloat16* __restrict__ outh, __nv_bfloat16* __restrict__ outl)
{
    extern __shared__ char dsmem[];
    uintptr_t pb = ((uintptr_t)dsmem + 1023) & ~(uintptr_t)1023;
    char* buf = (char*)pb;
    const int tid = threadIdx.x;
    const int wid = tid >> 5;
    const int lane = tid & 31;
    const int bh = blockIdx.y;
    const int b_ = bh >> 4;
    const int h_ = bh & (HH - 1);
    const int q0 = blockIdx.x * 128;

#if HAS_TCGEN05
    const int sp = wid & 3;
    const int chf = wid >> 2;
    const uint32_t sbuf = smem_u32(buf);
    const uint32_t ctrl = sbuf + FL_CT;
    int* msk_s = (int*)(buf + FL_MS);
    float* lpart = (float*)(buf + FL_CT + 64);

    if (wid == 0) TCGEN05_ALLOC(ctrl, 512);
    if (tid == 0) { MBARRIER_INIT(ctrl + 8, 1); MBARRIER_INIT(ctrl + 16, 1); }
    __syncthreads();
    uint32_t tmem;
    asm volatile("ld.shared.b32 %0, [%1];" : "=r"(tmem) : "r"(ctrl));

    auto load_kv = [&](int kb, int st) {
        const uint32_t sbK = sbuf + FL_K + (uint32_t)st * 16384;
        const uint32_t sbV = sbuf + FL_VT + (uint32_t)st * 16384;
#pragma unroll
        for (int j = 0; j < 4; j++) {
            int u = tid + j * 256;
            int r = u >> 3, g = u & 7;
            CP_ASYNC16(sbK + swz128((uint32_t)(r * 128 + g * 16)),
                       kg + ((size_t)(bh * SS + kb * 128 + r)) * HD + g * 8);
        }
#pragma unroll
        for (int j = 0; j < 4; j++) {
            int u = tid + j * 256;
            int d = u >> 4, g = u & 15;
            int key0 = g * 8;
            uint32_t o = (uint32_t)(((key0 >> 6) * 8 + (d >> 3)) * 1024 + (d & 7) * 128 + (key0 & 63) * 2);
            CP_ASYNC16(sbV + swz128(o),
                       vt + ((size_t)(bh * HD + d)) * SS + kb * 128 + key0);
        }
    };

#pragma unroll
    for (int j = 0; j < 4; j++) {
        int u = tid + j * 256;
        int r = u >> 3, g = u & 7;
        CP_ASYNC16(sbuf + FL_Q + swz128((uint32_t)(r * 128 + g * 16)),
                   qg + ((size_t)(bh * SS + q0 + r)) * HD + g * 8);
    }
#pragma unroll
    for (int j = 0; j < 2; j++)
        CP_ASYNC16(sbuf + FL_MS + tid * 16 + j * 4096,
                   mask + b_ * SS + tid * 4 + j * 1024);
    load_kv(0, 0);
    CP_COMMIT();
    load_kv(1, 1);
    CP_COMMIT();

    const uint64_t dQ = make_desc_sw128(sbuf + FL_Q);
    const uint64_t dP = make_desc_sw128(sbuf + FL_P);
    const int pOff[8] = {0, 2, 4, 6, 1024, 1026, 1028, 1030};
    const int vOff[8] = {0, 2, 4, 6, 512, 514, 516, 518};

    CP_WAIT(1);
    __syncthreads();
    FENCE_ASYNC_SHARED();
    if (wid == 0 && elect_one_pred()) {
        uint64_t dK = make_desc_sw128(sbuf + FL_K);
#pragma unroll
        for (int s = 0; s < 4; s++)
            mma_bf16_ss(tmem, dQ + s * 2, dK + s * 2, GEMM_IDESC, s != 0);
        TCGEN05_COMMIT(ctrl + 8);
    }

    float lsum = 0.0f;
    int phS = 0, phO = 0;
    const int r = sp * 32 + lane;

    for (int k = 0; k < NKB; k++) {
        const int st = k % 3;
        const uint32_t sbase = (uint32_t)(k & 1) * 128;

        // wait S_k
        MBARRIER_WAIT_PARITY(ctrl + 8, phS);
        phS ^= 1;
        TCGEN05_FENCE_AFTER();

        // LDTM both halves, single wait
        uint32_t sr[64];
        TCGEN05_LD_X32(sr, tmem + sbase + chf * 64);
        TCGEN05_LD_X32(sr + 32, tmem + sbase + chf * 64 + 32);
        TCGEN05_WAIT_LD();

        // exp into registers
        uint32_t ppk[32];
        const int cbase = k * 128 + chf * 64;
#pragma unroll
        for (int j = 0; j < 32; j++) {
            float p0 = msk_s[cbase + 2 * j]     ? __expf(__uint_as_float(sr[2 * j])     * 0.125f) : 0.0f;
            float p1 = msk_s[cbase + 2 * j + 1] ? __expf(__uint_as_float(sr[2 * j + 1]) * 0.125f) : 0.0f;
            __nv_bfloat16 bp0 = __float2bfloat16(p0), bp1 = __float2bfloat16(p1);
            ppk[j] = pack_bf2(bp0, bp1);
            lsum += __bfloat162float(bp0) + __bfloat162float(bp1);
        }

        // wait PV_{k-1}: frees P buffer and the stage for block k+2
        if (k > 0) { MBARRIER_WAIT_PARITY(ctrl + 16, phO); phO ^= 1; }
        if (k + 2 < NKB) { load_kv(k + 2, (k + 2) % 3); CP_COMMIT(); }

        // EARLY S_{k+1} issue: wait for K_{k+1}, issue before P-store/PV_k
        if (k + 1 < NKB) {
            if (k + 2 < NKB) CP_WAIT(1);
            else             CP_WAIT(0);
            __syncthreads();
            FENCE_ASYNC_SHARED();
            if (wid == 0 && elect_one_pred()) {
                uint64_t dK = make_desc_sw128(sbuf + FL_K + (uint32_t)((k + 1) % 3) * 16384);
                uint32_t dst = tmem + ((k + 1) & 1) * 128;
#pragma unroll
                for (int s = 0; s < 4; s++)
                    mma_bf16_ss(dst, dQ + s * 2, dK + s * 2, GEMM_IDESC, s != 0);
                TCGEN05_COMMIT(ctrl + 8);
            }
        }

        // write P
#pragma unroll
        for (int h2 = 0; h2 < 2; h2++) {
            uint32_t pbo = (uint32_t)((chf * 16 + (r >> 3)) * 1024 + (r & 7) * 128 + h2 * 64);
#pragma unroll
            for (int j = 0; j < 4; j++)
                *(uint4*)(buf + FL_P + swz128(pbo + j * 16)) =
                    make_uint4(ppk[h2 * 16 + 4 * j], ppk[h2 * 16 + 4 * j + 1],
                               ppk[h2 * 16 + 4 * j + 2], ppk[h2 * 16 + 4 * j + 3]);
        }
        TCGEN05_FENCE_BEFORE();
        FENCE_ASYNC_SHARED();
        __syncthreads();

        // PV_k
        if (wid == 0 && elect_one_pred()) {
            uint64_t dVT = make_desc_sw128(sbuf + FL_VT + (uint32_t)st * 16384);
#pragma unroll
            for (int s = 0; s < 8; s++)
                mma_bf16_ss(tmem + 256, dP + pOff[s], dVT + vOff[s], IDESC_N64,
                            !(k == 0 && s == 0));
            TCGEN05_COMMIT(ctrl + 16);
        }
    }

    MBARRIER_WAIT_PARITY(ctrl + 16, phO);
    TCGEN05_FENCE_AFTER();
    lpart[chf * 128 + r] = lsum;
    __syncthreads();

    if (wid < 4) {
        uint32_t orr[64];
        TCGEN05_LD_X32(orr, tmem + 256);
        TCGEN05_LD_X32(orr + 32, tmem + 288);
        TCGEN05_WAIT_LD();
        TCGEN05_FENCE_BEFORE();
        float inv = 1.0f / (lpart[r] + lpart[128 + r]);
        size_t base = ((size_t)(b_ * SS + q0 + r)) * DD + h_ * HD;
#pragma unroll
        for (int j8 = 0; j8 < 8; j8++) {
            uint32_t hw[4], lw[4];
#pragma unroll
            for (int q = 0; q < 4; q++) {
                int j = j8 * 8 + q * 2;
                float v0 = __uint_as_float(orr[j])     * inv;
                float v1 = __uint_as_float(orr[j + 1]) * inv;
                __nv_bfloat16 h0 = __float2bfloat16(v0), h1 = __float2bfloat16(v1);
                hw[q] = pack_bf2(h0, h1);
                lw[q] = pack_bf2(__float2bfloat16(v0 - __bfloat162float(h0)),
                                 __float2bfloat16(v1 - __bfloat162float(h1)));
            }
            *(uint4*)(outh + base + j8 * 8) = make_uint4(hw[0], hw[1], hw[2], hw[3]);
            *(uint4*)(outl + base + j8 * 8) = make_uint4(lw[0], lw[1], lw[2], lw[3]);
        }
    }
    __syncthreads();
    if (tid == 0) { MBARRIER_INVAL(ctrl + 8); MBARRIER_INVAL(ctrl + 16); }
    __syncthreads();
    if (wid == 0) TCGEN05_DEALLOC(tmem, 512);
#else
    if (tid < 128) {
        int rr = q0 + tid;
        float qr[64], o[64], l = 0.0f;
        for (int d = 0; d < 64; d++) {
            qr[d] = __bfloat162float(qg[((size_t)(bh * SS + rr)) * HD + d]);
            o[d] = 0.0f;
        }
        for (int key = 0; key < SS; key++) {
            if (!mask[b_ * SS + key]) continue;
            float s = 0.0f;
            const __nv_bfloat16* kp = kg + ((size_t)(bh * SS + key)) * HD;
            for (int d = 0; d < 64; d++) s += qr[d] * __bfloat162float(kp[d]);
            float pw = __expf(s * 0.125f);
            l += pw;
            for (int d = 0; d < 64; d++)
                o[d] += pw * __bfloat162float(vt[((size_t)(bh * HD + d)) * SS + key]);
        }
        float inv = 1.0f / l;
        for (int d = 0; d < 64; d++) {
            float v = o[d] * inv;
            __nv_bfloat16 h = __float2bfloat16(v);
            size_t od = ((size_t)(b_ * SS + rr)) * DD + h_ * HD + d;
            outh[od] = h;
            outl[od] = __float2bfloat16(v - __bfloat162float(h));
        }
    }
#endif
}

// ---------------- residual + bias + LN ----------------
template <bool SPLIT>
__global__ __launch_bounds__(256) void add_ln_kernel(
    const float* __restrict__ a, const float* __restrict__ b,
    const float* __restrict__ bias,
    const float* __restrict__ g, const float* __restrict__ be,
    float* __restrict__ out,
    __nv_bfloat16* __restrict__ oh, __nv_bfloat16* __restrict__ ol)
{
    __shared__ float sh[10];
    const int row = blockIdx.x;
    const int tid = threadIdx.x;
    const int wid = tid >> 5, lane = tid & 31;
    const size_t base = (size_t)row * DD + tid * 4;

    float4 av = *(const float4*)(a + base);
    float4 bv = *(const float4*)(b + base);
    float4 cv = *(const float4*)(bias + tid * 4);
    float4 t = make_float4(av.x + bv.x + cv.x, av.y + bv.y + cv.y,
                           av.z + bv.z + cv.z, av.w + bv.w + cv.w);
    float s = t.x + t.y + t.z + t.w;
#pragma unroll
    for (int off = 16; off >= 1; off >>= 1) s += __shfl_xor_sync(0xffffffffu, s, off);
    if (lane == 0) sh[wid] = s;
    __syncthreads();
    if (tid == 0) {
        float t2 = 0.f;
#pragma unroll
        for (int w = 0; w < 8; w++) t2 += sh[w];
        sh[8] = t2 * (1.0f / 1024.0f);
    }
    __syncthreads();
    float mu = sh[8];
    float dx = t.x - mu, dy = t.y - mu, dz = t.z - mu, dw = t.w - mu;
    float sq = dx * dx + dy * dy + dz * dz + dw * dw;
#pragma unroll
    for (int off = 16; off >= 1; off >>= 1) sq += __shfl_xor_sync(0xffffffffu, sq, off);
    if (lane == 0) sh[wid] = sq;
    __syncthreads();
    if (tid == 0) {
        float t2 = 0.f;
#pragma unroll
        for (int w = 0; w < 8; w++) t2 += sh[w];
        sh[9] = rsqrtf(t2 * (1.0f / 1024.0f) + 1e-5f);
    }
    __syncthreads();
    float inv = sh[9];
    float4 gv = *(const float4*)(g + tid * 4);
    float4 bev = *(const float4*)(be + tid * 4);
    float4 r = make_float4(dx * inv * gv.x + bev.x, dy * inv * gv.y + bev.y,
                           dz * inv * gv.z + bev.z, dw * inv * gv.w + bev.w);
    *(float4*)(out + base) = r;
    if (SPLIT) {
        __nv_bfloat16 h0 = __float2bfloat16(r.x), h1 = __float2bfloat16(r.y);
        __nv_bfloat16 h2 = __float2bfloat16(r.z), h3 = __float2bfloat16(r.w);
        *(uint2*)(oh + base) = make_uint2(pack_bf2(h0, h1), pack_bf2(h2, h3));
        *(uint2*)(ol + base) = make_uint2(
            pack_bf2(__float2bfloat16(r.x - __bfloat162float(h0)),
                     __float2bfloat16(r.y - __bfloat162float(h1))),
            pack_bf2(__float2bfloat16(r.z - __bfloat162float(h2)),
                     __float2bfloat16(r.w - __bfloat162float(h3))));
    }
}

// ---------------------------------------------------------------------------
extern "C" void kernel_launch(void* const* d_in, const int* in_sizes, int n_in,
                              void* d_out, int out_size)
{
    const float* x   = (const float*)d_in[0];
    const int*   msk = (const int*)d_in[1];
    const float* Wq  = (const float*)d_in[2];
    const float* bq  = (const float*)d_in[3];
    const float* Wk  = (const float*)d_in[4];
    const float* bk  = (const float*)d_in[5];
    const float* Wv  = (const float*)d_in[6];
    const float* bv  = (const float*)d_in[7];
    const float* Wo  = (const float*)d_in[8];
    const float* bo  = (const float*)d_in[9];
    const float* W1  = (const float*)d_in[10];
    const float* b1  = (const float*)d_in[11];
    const float* W2  = (const float*)d_in[12];
    const float* b2  = (const float*)d_in[13];
    const float* g1  = (const float*)d_in[14];
    const float* be1 = (const float*)d_in[15];
    const float* g2  = (const float*)d_in[16];
    const float* be2 = (const float*)d_in[17];
    float* out = (float*)d_out;

    __nv_bfloat16 *xh, *xl, *qh, *kh, *vh, *vt, *oh, *ol, *hb, *hl, *fh, *fl, *wh, *wl;
    float *f32a, *f32b, *f32c;
    cudaGetSymbolAddress((void**)&xh, g_xh);
    cudaGetSymbolAddress((void**)&xl, g_xl);
    cudaGetSymbolAddress((void**)&qh, g_qh);
    cudaGetSymbolAddress((void**)&kh, g_kh);
    cudaGetSymbolAddress((void**)&vh, g_vh);
    cudaGetSymbolAddress((void**)&vt, g_vt);
    cudaGetSymbolAddress((void**)&oh, g_oh);
    cudaGetSymbolAddress((void**)&ol, g_ol);
    cudaGetSymbolAddress((void**)&hb, g_hb);
    cudaGetSymbolAddress((void**)&hl, g_hl);
    cudaGetSymbolAddress((void**)&fh, g_fh);
    cudaGetSymbolAddress((void**)&fl, g_fl);
    cudaGetSymbolAddress((void**)&wh, g_wh);
    cudaGetSymbolAddress((void**)&wl, g_wl);
    cudaGetSymbolAddress((void**)&f32a, g_f32a);
    cudaGetSymbolAddress((void**)&f32b, g_f32b);
    cudaGetSymbolAddress((void**)&f32c, g_f32c);

    cudaFuncSetAttribute(gemm_bf<0>, cudaFuncAttributeMaxDynamicSharedMemorySize, GEMM_SMEM_BYTES);
    cudaFuncSetAttribute(gemm_bf<1>, cudaFuncAttributeMaxDynamicSharedMemorySize, GEMM_SMEM_BYTES);
    cudaFuncSetAttribute(gemm_bf<2>, cudaFuncAttributeMaxDynamicSharedMemorySize, GEMM_SMEM_BYTES);
    cudaFuncSetAttribute(flash_tc_kernel, cudaFuncAttributeMaxDynamicSharedMemorySize, FL_SMEM);

    dim3 blk(256);
    dim3 pw(32, 8);

    // x -> bf16 hi/lo
    split_kernel<<<(size_t)MM * DD / 1024, blk>>>(x, xh, xl);

    // weights -> transposed bf16 hi/lo
    prep_w_kernel<<<dim3(DD / 32, DD / 32), pw>>>(Wq, wh + WQ_OFF, wl + WQ_OFF, DD, DD);
    prep_w_kernel<<<dim3(DD / 32, DD / 32), pw>>>(Wk, wh + WK_OFF, wl + WK_OFF, DD, DD);
    prep_w_kernel<<<dim3(DD / 32, DD / 32), pw>>>(Wv, wh + WV_OFF, wl + WV_OFF, DD, DD);
    prep_w_kernel<<<dim3(DD / 32, DD / 32), pw>>>(Wo, wh + WO_OFF, wl + WO_OFF, DD, DD);
    prep_w_kernel<<<dim3(FF / 32, DD / 32), pw>>>(W1, wh + W1_OFF, wl + W1_OFF, DD, FF);
    prep_w_kernel<<<dim3(DD / 32, FF / 32), pw>>>(W2, wh + W2_OFF, wl + W2_OFF, FF, DD);

    // QKV combined (N=3072): 256x128 tiles
    gemm_bf<2><<<dim3(24, 32), blk, GEMM_SMEM_BYTES>>>(
        xh, xl, wh + WQ_OFF, wl + WQ_OFF,
        nullptr, nullptr, nullptr, qh, kh, vh, bq, bk, bv, MM, 3 * DD, DD);

    // V -> V^T
    transpose_v_kernel<<<dim3(SS / 64, BB * HH), blk>>>(vh, vt);

    // pipelined flash attention
    flash_tc_kernel<<<dim3(SS / 128, BB * HH), blk, FL_SMEM>>>(qh, kh, vt, msk, oh, ol);

    // O projection (fp32 out, bias folded into LN)
    gemm_bf<0><<<dim3(8, 32), blk, GEMM_SMEM_BYTES>>>(
        oh, ol, wh + WO_OFF, wl + WO_OFF,
        f32a, nullptr, nullptr, nullptr, nullptr, nullptr, nullptr, nullptr, nullptr,
        MM, DD, DD);

    // h = LN(x + o + bo): fp32 + bf16 split
    add_ln_kernel<true><<<MM, blk>>>(x, f32a, bo, g1, be1, f32b, hb, hl);

    // FFN1: relu(h W1 + b1) -> bf16 hi/lo
    gemm_bf<1><<<dim3(32, 32), blk, GEMM_SMEM_BYTES>>>(
        hb, hl, wh + W1_OFF, wl + W1_OFF,
        nullptr, fh, fl, nullptr, nullptr, nullptr, b1, nullptr, nullptr, MM, FF, DD);

    // FFN2 (fp32 out)
    gemm_bf<0><<<dim3(8, 32), blk, GEMM_SMEM_BYTES>>>(
        fh, fl, wh + W2_OFF, wl + W2_OFF,
        f32c, nullptr, nullptr, nullptr, nullptr, nullptr, nullptr, nullptr, nullptr,
        MM, DD, FF);

    // out = LN(h + ffn + b2)
    add_ln_kernel<false><<<MM, blk>>>(f32b, f32c, b2, g2, be2, out, nullptr, nullptr);
}

// round 15
// speedup vs baseline: 1.1169x; 1.0168x over previous
#include <cuda_runtime.h>
#include <cuda.h>
#include <cuda_bf16.h>
#include <math.h>
#include <stdint.h>

constexpr int BB = 4;
constexpr int SS = 2048;
constexpr int DD = 1024;
constexpr int HH = 16;
constexpr int HD = 64;
constexpr int FF = 4096;
constexpr int MM = BB * SS;

#if defined(__CUDA_ARCH_FEAT_SM103_ALL) || defined(__CUDA_ARCH_FEAT_SM100_ALL)
#define HAS_TCGEN05 1
#else
#define HAS_TCGEN05 0
#endif

// ---------------- device scratch ----------------
__device__ __nv_bfloat16 g_xh[(size_t)MM * DD];
__device__ __nv_bfloat16 g_xl[(size_t)MM * DD];
__device__ __nv_bfloat16 g_qh[(size_t)MM * DD];
__device__ __nv_bfloat16 g_kh[(size_t)MM * DD];
__device__ __nv_bfloat16 g_vh[(size_t)MM * DD];
__device__ __nv_bfloat16 g_vt[(size_t)MM * DD];
__device__ __nv_bfloat16 g_oh[(size_t)MM * DD];
__device__ __nv_bfloat16 g_ol[(size_t)MM * DD];
__device__ __nv_bfloat16 g_hb[(size_t)MM * DD];
__device__ __nv_bfloat16 g_hl[(size_t)MM * DD];
__device__ __nv_bfloat16 g_fh[(size_t)MM * FF];
__device__ __nv_bfloat16 g_fl[(size_t)MM * FF];
__device__ float g_f32a[(size_t)MM * DD];
__device__ float g_f32b[(size_t)MM * DD];
__device__ float g_f32c[(size_t)MM * DD];

constexpr size_t WQ_OFF = 0;
constexpr size_t WK_OFF = 1048576;
constexpr size_t WV_OFF = 2097152;
constexpr size_t WO_OFF = 3145728;
constexpr size_t W1_OFF = 4194304;
constexpr size_t W2_OFF = 8388608;
constexpr size_t WTOT   = 12582912;
__device__ __nv_bfloat16 g_wh[WTOT];
__device__ __nv_bfloat16 g_wl[WTOT];

// ---------------- helpers ----------------
__device__ __forceinline__ uint32_t smem_u32(const void* p) {
    uint32_t a;
    asm("{ .reg .u64 t; cvta.to.shared.u64 t, %1; cvt.u32.u64 %0, t; }" : "=r"(a) : "l"(p));
    return a;
}
__device__ __forceinline__ uint32_t swz128(uint32_t off) { return off ^ ((off >> 3) & 0x70); }
__device__ __forceinline__ uint32_t pack_bf2(__nv_bfloat16 a, __nv_bfloat16 b) {
    __nv_bfloat162 t; t.x = a; t.y = b; return *(uint32_t*)&t;
}
#define CP_ASYNC16(saddr, gptr) \
    asm volatile("cp.async.cg.shared.global [%0], [%1], 16;" \
        :: "r"((uint32_t)(saddr)), "l"(gptr) : "memory")
#define CP_COMMIT() asm volatile("cp.async.commit_group;" ::: "memory")
#define CP_WAIT(n)  asm volatile("cp.async.wait_group %0;" :: "n"(n) : "memory")

#if HAS_TCGEN05
__device__ __forceinline__ uint32_t elect_one_pred() {
    uint32_t pred;
    asm volatile("{\n\t.reg .pred p;\n\telect.sync _|p, 0xFFFFFFFF;\n\tselp.b32 %0, 1, 0, p;\n\t}" : "=r"(pred));
    return pred;
}
__device__ __forceinline__ uint32_t cluster_rank() {
    uint32_t r;
    asm("mov.u32 %0, %%cluster_ctarank;" : "=r"(r));
    return r;
}
#define TCGEN05_ALLOC(smem_addr, nCols) \
    asm volatile("tcgen05.alloc.cta_group::1.sync.aligned.shared::cta.b32 [%0], %1;" \
        :: "r"((uint32_t)(smem_addr)), "r"((uint32_t)(nCols)) : "memory")
#define TCGEN05_DEALLOC(tmem_addr, nCols) \
    asm volatile("tcgen05.dealloc.cta_group::1.sync.aligned.b32 %0, %1;" \
        :: "r"(tmem_addr), "r"((uint32_t)(nCols)))
#define TCGEN05_COMMIT(mbar) \
    asm volatile("tcgen05.commit.cta_group::1.mbarrier::arrive::one.shared::cluster.b64 [%0];" \
        :: "r"((uint32_t)(mbar)) : "memory")
#define TCGEN05_COMMIT_MC(mbar, mask) \
    asm volatile("tcgen05.commit.cta_group::1.mbarrier::arrive::one.shared::cluster.multicast::cluster.b64 [%0], %1;" \
        :: "r"((uint32_t)(mbar)), "h"((uint16_t)(mask)) : "memory")
#define TCGEN05_WAIT_LD()  asm volatile("tcgen05.wait::ld.sync.aligned;" ::: "memory")
#define TCGEN05_FENCE_BEFORE() asm volatile("tcgen05.fence::before_thread_sync;" ::: "memory")
#define TCGEN05_FENCE_AFTER()  asm volatile("tcgen05.fence::after_thread_sync;" ::: "memory")
#define FENCE_ASYNC_SHARED() asm volatile("fence.proxy.async.shared::cta;" ::: "memory")
#define MBARRIER_INIT(mbar, cnt) \
    asm volatile("mbarrier.init.shared.b64 [%0], %1;" :: "r"((uint32_t)(mbar)), "r"((uint32_t)(cnt)) : "memory")
#define MBARRIER_INVAL(mbar) \
    asm volatile("mbarrier.inval.shared.b64 [%0];" :: "r"((uint32_t)(mbar)) : "memory")
#define MBARRIER_EXPECT_TX(mbar, bytes) \
    asm volatile("mbarrier.arrive.expect_tx.shared.b64 _, [%0], %1;" \
        :: "r"((uint32_t)(mbar)), "r"((uint32_t)(bytes)) : "memory")
#define CLUSTER_SYNC() do { \
    asm volatile("barrier.cluster.arrive.aligned;" ::: "memory"); \
    asm volatile("barrier.cluster.wait.aligned;" ::: "memory"); \
} while (0)
#define TMA_LOAD_2D_MC(smem, mapp, cx, cy, mbar, mask) \
    asm volatile("cp.async.bulk.tensor.2d.shared::cluster.global.tile.mbarrier::complete_tx::bytes.multicast::cluster " \
        "[%0], [%1, {%2, %3}], [%4], %5;" \
        :: "r"((uint32_t)(smem)), "l"(mapp), "r"((int)(cx)), "r"((int)(cy)), \
           "r"((uint32_t)(mbar)), "h"((uint16_t)(mask)) : "memory")
#define MBARRIER_WAIT_PARITY(mbar, parity) do {                                    \
    uint32_t _mb = (uint32_t)(mbar);                                               \
    uint32_t _pa = (uint32_t)(parity);                                             \
    uint32_t _done;                                                                \
    asm volatile(                                                                  \
        "{\n\t.reg .pred p;\n\t"                                                   \
        "mbarrier.try_wait.parity.acquire.cta.shared::cta.b64 p, [%1], %2;\n\t"    \
        "selp.b32 %0, 1, 0, p;\n\t}"                                               \
        : "=r"(_done) : "r"(_mb), "r"(_pa) : "memory");                            \
    if (!_done) {                                                                  \
        asm volatile(                                                              \
            "{\n\t.reg .pred P1;\n\t"                                              \
            "WL_%=:\n\t"                                                           \
            "mbarrier.try_wait.parity.acquire.cta.shared::cta.b64 P1, [%0], %1, 0x989680;\n\t" \
            "@P1 bra.uni WD_%=;\n\t"                                               \
            "bra.uni WL_%=;\n\t"                                                   \
            "WD_%=:\n\t}"                                                          \
            :: "r"(_mb), "r"(_pa) : "memory");                                     \
    }                                                                              \
} while (0)
#define TCGEN05_LD_X32(r, addr) \
    asm volatile( \
        "tcgen05.ld.sync.aligned.32x32b.x32.b32 " \
        "{%0, %1, %2, %3, %4, %5, %6, %7, " \
        " %8, %9, %10, %11, %12, %13, %14, %15, " \
        " %16, %17, %18, %19, %20, %21, %22, %23, " \
        " %24, %25, %26, %27, %28, %29, %30, %31}, [%32];" \
        : "=r"((r)[0]),  "=r"((r)[1]),  "=r"((r)[2]),  "=r"((r)[3]), \
          "=r"((r)[4]),  "=r"((r)[5]),  "=r"((r)[6]),  "=r"((r)[7]), \
          "=r"((r)[8]),  "=r"((r)[9]),  "=r"((r)[10]), "=r"((r)[11]), \
          "=r"((r)[12]), "=r"((r)[13]), "=r"((r)[14]), "=r"((r)[15]), \
          "=r"((r)[16]), "=r"((r)[17]), "=r"((r)[18]), "=r"((r)[19]), \
          "=r"((r)[20]), "=r"((r)[21]), "=r"((r)[22]), "=r"((r)[23]), \
          "=r"((r)[24]), "=r"((r)[25]), "=r"((r)[26]), "=r"((r)[27]), \
          "=r"((r)[28]), "=r"((r)[29]), "=r"((r)[30]), "=r"((r)[31]) \
        : "r"(addr))

__device__ __forceinline__ uint64_t make_desc_sw128(uint32_t addr) {
    constexpr uint64_t BASE =
        (uint64_t(2) << 61) | (uint64_t(1) << 46) | (uint64_t(64) << 32) | (uint64_t(1) << 16);
    return BASE | ((uint64_t)(addr >> 4) & 0x3FFF);
}
__device__ __forceinline__ void mma_bf16_ss(uint32_t d, uint64_t ad, uint64_t bd,
                                            uint32_t idesc, bool acc) {
    uint32_t en = acc ? 1u : 0u;
    asm volatile(
        "{\n\t.reg .pred p;\n\t"
        "setp.ne.u32 p, %5, 0;\n\t"
        "tcgen05.mma.cta_group::1.kind::f16 [%0], %1, %2, %3, {%4, %4, %4, %4}, p;\n\t}"
        :: "r"(d), "l"(ad), "l"(bd), "r"(idesc), "r"(0u), "r"(en) : "memory");
}
#endif

constexpr uint32_t GEMM_IDESC =
    (1u << 4) | (1u << 7) | (1u << 10) | ((128 / 8) << 17) | ((128 / 16) << 24);
constexpr uint32_t IDESC_N64 =
    (1u << 4) | (1u << 7) | (1u << 10) | ((64 / 8) << 17) | ((128 / 16) << 24);

// ---------------- weight prep ----------------
__global__ void prep_w_kernel(const float* __restrict__ W,
                              __nv_bfloat16* __restrict__ Bh,
                              __nv_bfloat16* __restrict__ Bl, int K, int N)
{
    __shared__ float t[32][33];
    const int n0 = blockIdx.x * 32, k0 = blockIdx.y * 32;
#pragma unroll
    for (int i = 0; i < 4; i++)
        t[threadIdx.y + i * 8][threadIdx.x] =
            W[(size_t)(k0 + threadIdx.y + i * 8) * N + n0 + threadIdx.x];
    __syncthreads();
#pragma unroll
    for (int i = 0; i < 4; i++) {
        int n = threadIdx.y + i * 8;
        float v = t[threadIdx.x][n];
        __nv_bfloat16 h = __float2bfloat16(v);
        size_t idx = (size_t)(n0 + n) * K + k0 + threadIdx.x;
        Bh[idx] = h;
        Bl[idx] = __float2bfloat16(v - __bfloat162float(h));
    }
}

// fp32 -> bf16 hi/lo split
__global__ __launch_bounds__(256) void split_kernel(
    const float* __restrict__ in,
    __nv_bfloat16* __restrict__ oh, __nv_bfloat16* __restrict__ ol)
{
    size_t i = ((size_t)blockIdx.x * 256 + threadIdx.x) * 4;
    float4 v = *(const float4*)(in + i);
    __nv_bfloat16 h0 = __float2bfloat16(v.x), h1 = __float2bfloat16(v.y);
    __nv_bfloat16 h2 = __float2bfloat16(v.z), h3 = __float2bfloat16(v.w);
    *(uint2*)(oh + i) = make_uint2(pack_bf2(h0, h1), pack_bf2(h2, h3));
    *(uint2*)(ol + i) = make_uint2(
        pack_bf2(__float2bfloat16(v.x - __bfloat162float(h0)),
                 __float2bfloat16(v.y - __bfloat162float(h1))),
        pack_bf2(__float2bfloat16(v.z - __bfloat162float(h2)),
                 __float2bfloat16(v.w - __bfloat162float(h3))));
}

// V transpose
__global__ __launch_bounds__(256) void transpose_v_kernel(
    const __nv_bfloat16* __restrict__ vh, __nv_bfloat16* __restrict__ vt)
{
    __shared__ __nv_bfloat16 t[64][72];
    const int bh = blockIdx.y;
    const int s0 = blockIdx.x * 64;
    const int r = threadIdx.x >> 2;
    const int c = (threadIdx.x & 3) * 16;
    const __nv_bfloat16* src = vh + ((size_t)(bh * SS + s0 + r)) * HD + c;
    *(uint4*)(&t[r][c])     = *(const uint4*)(src);
    *(uint4*)(&t[r][c + 8]) = *(const uint4*)(src + 8);
    __syncthreads();
    __nv_bfloat16* dst = vt + ((size_t)(bh * HD + r)) * SS + s0 + c;
    __nv_bfloat16 tmp[16];
#pragma unroll
    for (int j = 0; j < 16; j++) tmp[j] = t[c + j][r];
    *(uint4*)(dst)     = *(uint4*)(tmp);
    *(uint4*)(dst + 8) = *(uint4*)(tmp + 8);
}

// ---------------------------------------------------------------------------
// GEMM: 256x128 tile, cluster(2,1,1): A via TMA 2D multicast, B via cp.async.
// ---------------------------------------------------------------------------
constexpr int GEMM_STAGE = 98304;
constexpr int GEMM_SMEM_BYTES = 2 * GEMM_STAGE + 1024;

template <int EPI>
__global__ __launch_bounds__(256, 1) __cluster_dims__(2, 1, 1) void gemm_bf(
    const __grid_constant__ CUtensorMap tmAh, const __grid_constant__ CUtensorMap tmAl,
    const __nv_bfloat16* __restrict__ Ah, const __nv_bfloat16* __restrict__ Al,
    const __nv_bfloat16* __restrict__ Bh, const __nv_bfloat16* __restrict__ Bl,
    float* __restrict__ Cf, __nv_bfloat16* __restrict__ Ch, __nv_bfloat16* __restrict__ Cl,
    __nv_bfloat16* __restrict__ D0, __nv_bfloat16* __restrict__ D1, __nv_bfloat16* __restrict__ D2,
    const float* __restrict__ bias0, const float* __restrict__ bias1, const float* __restrict__ bias2,
    int M, int N, int K)
{
    extern __shared__ char dsmem[];
    uintptr_t p = ((uintptr_t)dsmem + 1023) & ~(uintptr_t)1023;
    char* buf = (char*)p;
    const int tid = threadIdx.x;
    const int wid = tid >> 5;
    const int lane = tid & 31;
    const int m0 = blockIdx.y << 8;
    const int n0 = blockIdx.x << 7;

#if HAS_TCGEN05
    __shared__ alignas(16) unsigned long long ctrlq[6];
    const uint32_t sbuf = smem_u32(buf);
    const uint32_t ctrl = smem_u32(ctrlq);
    const uint32_t xr = cluster_rank();

    if (wid == 0) TCGEN05_ALLOC(ctrl, 256);
    if (tid == 0) {
        MBARRIER_INIT(ctrl + 8, 2);    // stage0 MMA-done (self + peer)
        MBARRIER_INIT(ctrl + 16, 2);   // stage1 MMA-done
        MBARRIER_INIT(ctrl + 24, 1);   // final
        MBARRIER_INIT(ctrl + 32, 1);   // stage0 A-data (tx)
        MBARRIER_INIT(ctrl + 40, 1);   // stage1 A-data (tx)
    }
    __syncthreads();
    CLUSTER_SYNC();
    uint32_t tmem;
    asm volatile("ld.shared.b32 %0, [%1];" : "=r"(tmem) : "r"(ctrl));

    const int NC = K >> 6;

    auto load_chunk = [&](int ck, int st) {
        const uint32_t sb = sbuf + (uint32_t)st * GEMM_STAGE;
        const int k0 = ck << 6;
        if (tid == 0) {
            MBARRIER_EXPECT_TX(ctrl + 32 + st * 8, 65536);
            TMA_LOAD_2D_MC(sb + xr * 16384, &tmAh, k0, m0 + xr * 128,
                           ctrl + 32 + st * 8, 0x3);
            TMA_LOAD_2D_MC(sb + 32768 + xr * 16384, &tmAl, k0, m0 + xr * 128,
                           ctrl + 32 + st * 8, 0x3);
        }
#pragma unroll
        for (int j = 0; j < 4; j++) {
            int u = tid + j * 256;
            int r = u >> 3, g = u & 7;
            uint32_t so = swz128((uint32_t)(r * 128 + g * 16));
            size_t bo = (size_t)(n0 + r) * K + k0 + g * 8;
            CP_ASYNC16(sb + 65536 + so, Bh + bo);
            CP_ASYNC16(sb + 81920 + so, Bl + bo);
        }
    };

    load_chunk(0, 0);
    CP_COMMIT();
    load_chunk(1, 1);
    CP_COMMIT();

    int ph[2] = {0, 0};
    int phD[2] = {0, 0};

    for (int i = 0; i < NC; i++) {
        const int st = i & 1;
        MBARRIER_WAIT_PARITY(ctrl + 32 + st * 8, phD[st]);
        phD[st] ^= 1;
        if (i < NC - 1) CP_WAIT(1);
        else            CP_WAIT(0);
        __syncthreads();
        FENCE_ASYNC_SHARED();

        if (wid == 0 && elect_one_pred()) {
            const uint32_t sb = sbuf + (uint32_t)st * GEMM_STAGE;
            uint64_t dBh = make_desc_sw128(sb + 65536);
            uint64_t dBl = make_desc_sw128(sb + 81920);
#pragma unroll
            for (int mt = 0; mt < 2; mt++) {
                uint64_t dAh = make_desc_sw128(sb + mt * 16384);
                uint64_t dAl = make_desc_sw128(sb + 32768 + mt * 16384);
                uint32_t dst = tmem + mt * 128;
#pragma unroll
                for (int ks = 0; ks < 4; ks++)
                    mma_bf16_ss(dst, dAh + ks * 2, dBh + ks * 2, GEMM_IDESC, !(i == 0 && ks == 0));
#pragma unroll
                for (int ks = 0; ks < 4; ks++)
                    mma_bf16_ss(dst, dAl + ks * 2, dBh + ks * 2, GEMM_IDESC, true);
#pragma unroll
                for (int ks = 0; ks < 4; ks++)
                    mma_bf16_ss(dst, dAh + ks * 2, dBl + ks * 2, GEMM_IDESC, true);
            }
            TCGEN05_COMMIT_MC(ctrl + 8 + st * 8, 0x3);
        }

        if (i + 2 < NC) {
            MBARRIER_WAIT_PARITY(ctrl + 8 + st * 8, ph[st]);
            ph[st] ^= 1;
            load_chunk(i + 2, st);
            CP_COMMIT();
        }
    }

    if (wid == 0 && elect_one_pred()) TCGEN05_COMMIT(ctrl + 24);
    MBARRIER_WAIT_PARITY(ctrl + 24, 0);
    TCGEN05_FENCE_AFTER();

    {
        const int sp = wid & 3;
        const int chf = wid >> 2;
#pragma unroll
        for (int mt = 0; mt < 2; mt++) {
            uint32_t r[64];
            TCGEN05_LD_X32(r, tmem + mt * 128 + chf * 64);
            TCGEN05_LD_X32(r + 32, tmem + mt * 128 + chf * 64 + 32);
            TCGEN05_WAIT_LD();
            TCGEN05_FENCE_BEFORE();

            const int row = m0 + mt * 128 + sp * 32 + lane;
            const int c0 = n0 + chf * 64;

            if (EPI == 0) {
                float* cp = Cf + (size_t)row * N + c0;
#pragma unroll
                for (int c = 0; c < 16; c++) {
                    float4 v;
                    v.x = __uint_as_float(r[4 * c + 0]);
                    v.y = __uint_as_float(r[4 * c + 1]);
                    v.z = __uint_as_float(r[4 * c + 2]);
                    v.w = __uint_as_float(r[4 * c + 3]);
                    *(float4*)(cp + 4 * c) = v;
                }
            } else if (EPI == 1) {
                size_t base = (size_t)row * N + c0;
#pragma unroll
                for (int j8 = 0; j8 < 8; j8++) {
                    uint32_t hw[4], lw[4];
#pragma unroll
                    for (int q = 0; q < 4; q++) {
                        int j = j8 * 8 + q * 2;
                        float v0 = fmaxf(__uint_as_float(r[j])     + bias0[c0 + j],     0.0f);
                        float v1 = fmaxf(__uint_as_float(r[j + 1]) + bias0[c0 + j + 1], 0.0f);
                        __nv_bfloat16 h0 = __float2bfloat16(v0), h1 = __float2bfloat16(v1);
                        hw[q] = pack_bf2(h0, h1);
                        lw[q] = pack_bf2(__float2bfloat16(v0 - __bfloat162float(h0)),
                                         __float2bfloat16(v1 - __bfloat162float(h1)));
                    }
                    *(uint4*)(Ch + base + j8 * 8) = make_uint4(hw[0], hw[1], hw[2], hw[3]);
                    *(uint4*)(Cl + base + j8 * 8) = make_uint4(lw[0], lw[1], lw[2], lw[3]);
                }
            } else {
                const int mat = c0 >> 10;
                const int lc = c0 & 1023;
                const float* bs = (mat == 0) ? bias0 : (mat == 1) ? bias1 : bias2;
                __nv_bfloat16* Dd = (mat == 0) ? D0 : (mat == 1) ? D1 : D2;
                const int h_ = lc >> 6;
                const int b_ = row >> 11;
                const int s_ = row & (SS - 1);
                size_t base = (((size_t)b_ * HH + h_) * SS + s_) * HD;
#pragma unroll
                for (int j8 = 0; j8 < 8; j8++) {
                    uint32_t hw[4];
#pragma unroll
                    for (int q = 0; q < 4; q++) {
                        int j = j8 * 8 + q * 2;
                        float v0 = __uint_as_float(r[j])     + bs[lc + j];
                        float v1 = __uint_as_float(r[j + 1]) + bs[lc + j + 1];
                        hw[q] = pack_bf2(__float2bfloat16(v0), __float2bfloat16(v1));
                    }
                    *(uint4*)(Dd + base + j8 * 8) = make_uint4(hw[0], hw[1], hw[2], hw[3]);
                }
            }
        }
    }

    __syncthreads();
    if (tid == 0) {
        MBARRIER_INVAL(ctrl + 8);
        MBARRIER_INVAL(ctrl + 16);
        MBARRIER_INVAL(ctrl + 24);
        MBARRIER_INVAL(ctrl + 32);
        MBARRIER_INVAL(ctrl + 40);
    }
    __syncthreads();
    if (wid == 0) TCGEN05_DEALLOC(tmem, 256);
    CLUSTER_SYNC();

#else  // FFMA fallback
    float* As = (float*)buf;
    float* Bs = As + 16 * 132;
    const int tx = tid & 15, ty = tid >> 4;
    for (int mt = 0; mt < 2; mt++) {
        const int mb = m0 + mt * 128;
        float acc[8][8];
#pragma unroll
        for (int i = 0; i < 8; i++)
#pragma unroll
            for (int j = 0; j < 8; j++) acc[i][j] = 0.0f;
        for (int k0 = 0; k0 < K; k0 += 16) {
            for (int it = 0; it < 8; it++) {
                int idx = tid + it * 256;
                int rr = idx >> 4, kk = idx & 15;
                As[kk * 132 + rr] =
                    __bfloat162float(Ah[(size_t)(mb + rr) * K + k0 + kk]) +
                    __bfloat162float(Al[(size_t)(mb + rr) * K + k0 + kk]);
                Bs[kk * 132 + rr] =
                    __bfloat162float(Bh[(size_t)(n0 + rr) * K + k0 + kk]) +
                    __bfloat162float(Bl[(size_t)(n0 + rr) * K + k0 + kk]);
            }
            __syncthreads();
#pragma unroll
            for (int k = 0; k < 16; k++) {
                float a[8], bb[8];
#pragma unroll
                for (int i = 0; i < 8; i++) a[i] = As[k * 132 + ty * 8 + i];
#pragma unroll
                for (int j = 0; j < 8; j++) bb[j] = Bs[k * 132 + tx * 8 + j];
#pragma unroll
                for (int i = 0; i < 8; i++)
#pragma unroll
                    for (int j = 0; j < 8; j++) acc[i][j] = fmaf(a[i], bb[j], acc[i][j]);
            }
            __syncthreads();
        }
#pragma unroll
        for (int i = 0; i < 8; i++) {
            int row = mb + ty * 8 + i;
#pragma unroll
            for (int j = 0; j < 8; j++) {
                int col = n0 + tx * 8 + j;
                float v = acc[i][j];
                if (EPI == 0) {
                    Cf[(size_t)row * N + col] = v;
                } else if (EPI == 1) {
                    v = fmaxf(v + bias0[col], 0.0f);
                    __nv_bfloat16 h = __float2bfloat16(v);
                    Ch[(size_t)row * N + col] = h;
                    Cl[(size_t)row * N + col] = __float2bfloat16(v - __bfloat162float(h));
                } else {
                    int mat = col >> 10, lc = col & 1023;
                    const float* bs = (mat == 0) ? bias0 : (mat == 1) ? bias1 : bias2;
                    __nv_bfloat16* Dd = (mat == 0) ? D0 : (mat == 1) ? D1 : D2;
                    float vv = v + bs[lc];
                    int h_ = lc >> 6, d = lc & 63;
                    int b_ = row >> 11, s_ = row & (SS - 1);
                    Dd[(((size_t)b_ * HH + h_) * SS + s_) * HD + d] = __float2bfloat16(vv);
                }
            }
        }
        __syncthreads();
    }
#endif
}

// ---------------------------------------------------------------------------
// Pipelined tcgen05 flash attention (unchanged; proven at 986us)
// ---------------------------------------------------------------------------
constexpr int FL_Q  = 0;
constexpr int FL_K  = 16384;
constexpr int FL_VT = 65536;
constexpr int FL_P  = 114688;
constexpr int FL_MS = 147456;
constexpr int FL_CT = 155648;
constexpr int FL_SMEM = FL_CT + 64 + 1024 + 1024;
constexpr int NKB = SS / 128;

__global__ __launch_bounds__(256, 1) void flash_tc_kernel(
    const __nv_bfloat16* __restrict__ qg, const __nv_bfloat16* __restrict__ kg,
    const __nv_bfloat16* __restrict__ vt, const int* __restrict__ mask,
    __nv_bfloat16* __restrict__ outh, __nv_bfloat16* __restrict__ outl)
{
    extern __shared__ char dsmem[];
    uintptr_t pb = ((uintptr_t)dsmem + 1023) & ~(uintptr_t)1023;
    char* buf = (char*)pb;
    const int tid = threadIdx.x;
    const int wid = tid >> 5;
    const int lane = tid & 31;
    const int bh = blockIdx.y;
    const int b_ = bh >> 4;
    const int h_ = bh & (HH - 1);
    const int q0 = blockIdx.x * 128;

#if HAS_TCGEN05
    const int sp = wid & 3;
    const int chf = wid >> 2;
    const uint32_t sbuf = smem_u32(buf);
    const uint32_t ctrl = sbuf + FL_CT;
    int* msk_s = (int*)(buf + FL_MS);
    float* lpart = (float*)(buf + FL_CT + 64);

    if (wid == 0) TCGEN05_ALLOC(ctrl, 512);
    if (tid == 0) { MBARRIER_INIT(ctrl + 8, 1); MBARRIER_INIT(ctrl + 16, 1); }
    __syncthreads();
    uint32_t tmem;
    asm volatile("ld.shared.b32 %0, [%1];" : "=r"(tmem) : "r"(ctrl));

    auto load_kv = [&](int kb, int st) {
        const uint32_t sbK = sbuf + FL_K + (uint32_t)st * 16384;
        const uint32_t sbV = sbuf + FL_VT + (uint32_t)st * 16384;
#pragma unroll
        for (int j = 0; j < 4; j++) {
            int u = tid + j * 256;
            int r = u >> 3, g = u & 7;
            CP_ASYNC16(sbK + swz128((uint32_t)(r * 128 + g * 16)),
                       kg + ((size_t)(bh * SS + kb * 128 + r)) * HD + g * 8);
        }
#pragma unroll
        for (int j = 0; j < 4; j++) {
            int u = tid + j * 256;
            int d = u >> 4, g = u & 15;
            int key0 = g * 8;
            uint32_t o = (uint32_t)(((key0 >> 6) * 8 + (d >> 3)) * 1024 + (d & 7) * 128 + (key0 & 63) * 2);
            CP_ASYNC16(sbV + swz128(o),
                       vt + ((size_t)(bh * HD + d)) * SS + kb * 128 + key0);
        }
    };

#pragma unroll
    for (int j = 0; j < 4; j++) {
        int u = tid + j * 256;
        int r = u >> 3, g = u & 7;
        CP_ASYNC16(sbuf + FL_Q + swz128((uint32_t)(r * 128 + g * 16)),
                   qg + ((size_t)(bh * SS + q0 + r)) * HD + g * 8);
    }
#pragma unroll
    for (int j = 0; j < 2; j++)
        CP_ASYNC16(sbuf + FL_MS + tid * 16 + j * 4096,
                   mask + b_ * SS + tid * 4 + j * 1024);
    load_kv(0, 0);
    CP_COMMIT();
    load_kv(1, 1);
    CP_COMMIT();

    const uint64_t dQ = make_desc_sw128(sbuf + FL_Q);
    const uint64_t dP = make_desc_sw128(sbuf + FL_P);
    const int pOff[8] = {0, 2, 4, 6, 1024, 1026, 1028, 1030};
    const int vOff[8] = {0, 2, 4, 6, 512, 514, 516, 518};

    CP_WAIT(1);
    __syncthreads();
    FENCE_ASYNC_SHARED();
    if (wid == 0 && elect_one_pred()) {
        uint64_t dK = make_desc_sw128(sbuf + FL_K);
#pragma unroll
        for (int s = 0; s < 4; s++)
            mma_bf16_ss(tmem, dQ + s * 2, dK + s * 2, GEMM_IDESC, s != 0);
        TCGEN05_COMMIT(ctrl + 8);
    }

    float lsum = 0.0f;
    int phS = 0, phO = 0;
    const int r = sp * 32 + lane;

    for (int k = 0; k < NKB; k++) {
        const int st = k % 3;
        const uint32_t sbase = (uint32_t)(k & 1) * 128;

        MBARRIER_WAIT_PARITY(ctrl + 8, phS);
        phS ^= 1;
        TCGEN05_FENCE_AFTER();

        uint32_t sr[64];
        TCGEN05_LD_X32(sr, tmem + sbase + chf * 64);
        TCGEN05_LD_X32(sr + 32, tmem + sbase + chf * 64 + 32);
        TCGEN05_WAIT_LD();

        uint32_t ppk[32];
        const int cbase = k * 128 + chf * 64;
#pragma unroll
        for (int j = 0; j < 32; j++) {
            float p0 = msk_s[cbase + 2 * j]     ? __expf(__uint_as_float(sr[2 * j])     * 0.125f) : 0.0f;
            float p1 = msk_s[cbase + 2 * j + 1] ? __expf(__uint_as_float(sr[2 * j + 1]) * 0.125f) : 0.0f;
            __nv_bfloat16 bp0 = __float2bfloat16(p0), bp1 = __float2bfloat16(p1);
            ppk[j] = pack_bf2(bp0, bp1);
            lsum += __bfloat162float(bp0) + __bfloat162float(bp1);
        }

        if (k > 0) { MBARRIER_WAIT_PARITY(ctrl + 16, phO); phO ^= 1; }
        if (k + 2 < NKB) { load_kv(k + 2, (k + 2) % 3); CP_COMMIT(); }

        if (k + 1 < NKB) {
            if (k + 2 < NKB) CP_WAIT(1);
            else             CP_WAIT(0);
            __syncthreads();
            FENCE_ASYNC_SHARED();
            if (wid == 0 && elect_one_pred()) {
                uint64_t dK = make_desc_sw128(sbuf + FL_K + (uint32_t)((k + 1) % 3) * 16384);
                uint32_t dst = tmem + ((k + 1) & 1) * 128;
#pragma unroll
                for (int s = 0; s < 4; s++)
                    mma_bf16_ss(dst, dQ + s * 2, dK + s * 2, GEMM_IDESC, s != 0);
                TCGEN05_COMMIT(ctrl + 8);
            }
        }

#pragma unroll
        for (int h2 = 0; h2 < 2; h2++) {
            uint32_t pbo = (uint32_t)((chf * 16 + (r >> 3)) * 1024 + (r & 7) * 128 + h2 * 64);
#pragma unroll
            for (int j = 0; j < 4; j++)
                *(uint4*)(buf + FL_P + swz128(pbo + j * 16)) =
                    make_uint4(ppk[h2 * 16 + 4 * j], ppk[h2 * 16 + 4 * j + 1],
                               ppk[h2 * 16 + 4 * j + 2], ppk[h2 * 16 + 4 * j + 3]);
        }
        TCGEN05_FENCE_BEFORE();
        FENCE_ASYNC_SHARED();
        __syncthreads();

        if (wid == 0 && elect_one_pred()) {
            uint64_t dVT = make_desc_sw128(sbuf + FL_VT + (uint32_t)st * 16384);
#pragma unroll
            for (int s = 0; s < 8; s++)
                mma_bf16_ss(tmem + 256, dP + pOff[s], dVT + vOff[s], IDESC_N64,
                            !(k == 0 && s == 0));
            TCGEN05_COMMIT(ctrl + 16);
        }
    }

    MBARRIER_WAIT_PARITY(ctrl + 16, phO);
    TCGEN05_FENCE_AFTER();
    lpart[chf * 128 + r] = lsum;
    __syncthreads();

    if (wid < 4) {
        uint32_t orr[64];
        TCGEN05_LD_X32(orr, tmem + 256);
        TCGEN05_LD_X32(orr + 32, tmem + 288);
        TCGEN05_WAIT_LD();
        TCGEN05_FENCE_BEFORE();
        float inv = 1.0f / (lpart[r] + lpart[128 + r]);
        size_t base = ((size_t)(b_ * SS + q0 + r)) * DD + h_ * HD;
#pragma unroll
        for (int j8 = 0; j8 < 8; j8++) {
            uint32_t hw[4], lw[4];
#pragma unroll
            for (int q = 0; q < 4; q++) {
                int j = j8 * 8 + q * 2;
                float v0 = __uint_as_float(orr[j])     * inv;
                float v1 = __uint_as_float(orr[j + 1]) * inv;
                __nv_bfloat16 h0 = __float2bfloat16(v0), h1 = __float2bfloat16(v1);
                hw[q] = pack_bf2(h0, h1);
                lw[q] = pack_bf2(__float2bfloat16(v0 - __bfloat162float(h0)),
                                 __float2bfloat16(v1 - __bfloat162float(h1)));
            }
            *(uint4*)(outh + base + j8 * 8) = make_uint4(hw[0], hw[1], hw[2], hw[3]);
            *(uint4*)(outl + base + j8 * 8) = make_uint4(lw[0], lw[1], lw[2], lw[3]);
        }
    }
    __syncthreads();
    if (tid == 0) { MBARRIER_INVAL(ctrl + 8); MBARRIER_INVAL(ctrl + 16); }
    __syncthreads();
    if (wid == 0) TCGEN05_DEALLOC(tmem, 512);
#else
    if (tid < 128) {
        int rr = q0 + tid;
        float qr[64], o[64], l = 0.0f;
        for (int d = 0; d < 64; d++) {
            qr[d] = __bfloat162float(qg[((size_t)(bh * SS + rr)) * HD + d]);
            o[d] = 0.0f;
        }
        for (int key = 0; key < SS; key++) {
            if (!mask[b_ * SS + key]) continue;
            float s = 0.0f;
            const __nv_bfloat16* kp = kg + ((size_t)(bh * SS + key)) * HD;
            for (int d = 0; d < 64; d++) s += qr[d] * __bfloat162float(kp[d]);
            float pw = __expf(s * 0.125f);
            l += pw;
            for (int d = 0; d < 64; d++)
                o[d] += pw * __bfloat162float(vt[((size_t)(bh * HD + d)) * SS + key]);
        }
        float inv = 1.0f / l;
        for (int d = 0; d < 64; d++) {
            float v = o[d] * inv;
            __nv_bfloat16 h = __float2bfloat16(v);
            size_t od = ((size_t)(b_ * SS + rr)) * DD + h_ * HD + d;
            outh[od] = h;
            outl[od] = __float2bfloat16(v - __bfloat162float(h));
        }
    }
#endif
}

// ---------------- residual + bias + LN ----------------
template <bool SPLIT>
__global__ __launch_bounds__(256) void add_ln_kernel(
    const float* __restrict__ a, const float* __restrict__ b,
    const float* __restrict__ bias,
    const float* __restrict__ g, const float* __restrict__ be,
    float* __restrict__ out,
    __nv_bfloat16* __restrict__ oh, __nv_bfloat16* __restrict__ ol)
{
    __shared__ float sh[10];
    const int row = blockIdx.x;
    const int tid = threadIdx.x;
    const int wid = tid >> 5, lane = tid & 31;
    const size_t base = (size_t)row * DD + tid * 4;

    float4 av = *(const float4*)(a + base);
    float4 bv = *(const float4*)(b + base);
    float4 cv = *(const float4*)(bias + tid * 4);
    float4 t = make_float4(av.x + bv.x + cv.x, av.y + bv.y + cv.y,
                           av.z + bv.z + cv.z, av.w + bv.w + cv.w);
    float s = t.x + t.y + t.z + t.w;
#pragma unroll
    for (int off = 16; off >= 1; off >>= 1) s += __shfl_xor_sync(0xffffffffu, s, off);
    if (lane == 0) sh[wid] = s;
    __syncthreads();
    if (tid == 0) {
        float t2 = 0.f;
#pragma unroll
        for (int w = 0; w < 8; w++) t2 += sh[w];
        sh[8] = t2 * (1.0f / 1024.0f);
    }
    __syncthreads();
    float mu = sh[8];
    float dx = t.x - mu, dy = t.y - mu, dz = t.z - mu, dw = t.w - mu;
    float sq = dx * dx + dy * dy + dz * dz + dw * dw;
#pragma unroll
    for (int off = 16; off >= 1; off >>= 1) sq += __shfl_xor_sync(0xffffffffu, sq, off);
    if (lane == 0) sh[wid] = sq;
    __syncthreads();
    if (tid == 0) {
        float t2 = 0.f;
#pragma unroll
        for (int w = 0; w < 8; w++) t2 += sh[w];
        sh[9] = rsqrtf(t2 * (1.0f / 1024.0f) + 1e-5f);
    }
    __syncthreads();
    float inv = sh[9];
    float4 gv = *(const float4*)(g + tid * 4);
    float4 bev = *(const float4*)(be + tid * 4);
    float4 r = make_float4(dx * inv * gv.x + bev.x, dy * inv * gv.y + bev.y,
                           dz * inv * gv.z + bev.z, dw * inv * gv.w + bev.w);
    *(float4*)(out + base) = r;
    if (SPLIT) {
        __nv_bfloat16 h0 = __float2bfloat16(r.x), h1 = __float2bfloat16(r.y);
        __nv_bfloat16 h2 = __float2bfloat16(r.z), h3 = __float2bfloat16(r.w);
        *(uint2*)(oh + base) = make_uint2(pack_bf2(h0, h1), pack_bf2(h2, h3));
        *(uint2*)(ol + base) = make_uint2(
            pack_bf2(__float2bfloat16(r.x - __bfloat162float(h0)),
                     __float2bfloat16(r.y - __bfloat162float(h1))),
            pack_bf2(__float2bfloat16(r.z - __bfloat162float(h2)),
                     __float2bfloat16(r.w - __bfloat162float(h3))));
    }
}

// ---------------------------------------------------------------------------
// Driver entry point resolved via runtime API (no -lcuda needed)
typedef CUresult (*PFN_encodeTiled)(
    CUtensorMap*, CUtensorMapDataType, cuuint32_t, void*,
    const cuuint64_t*, const cuuint64_t*, const cuuint32_t*, const cuuint32_t*,
    CUtensorMapInterleave, CUtensorMapSwizzle, CUtensorMapL2promotion,
    CUtensorMapFloatOOBfill);

static PFN_encodeTiled get_encode_fn() {
    void* fn = nullptr;
    cudaDriverEntryPointQueryResult st;
#if CUDART_VERSION >= 12000
    cudaGetDriverEntryPoint("cuTensorMapEncodeTiled", &fn, cudaEnableDefault, &st);
#else
    cudaGetDriverEntryPoint("cuTensorMapEncodeTiled", &fn, cudaEnableDefault);
#endif
    return (PFN_encodeTiled)fn;
}

static void make_map_bf16(PFN_encodeTiled enc, CUtensorMap* m, void* base,
                          uint64_t K, uint64_t rows) {
    cuuint64_t dims[2] = {K, rows};
    cuuint64_t strides[1] = {K * 2};
    cuuint32_t box[2] = {64, 128};
    cuuint32_t es[2] = {1, 1};
    enc(m, CU_TENSOR_MAP_DATA_TYPE_BFLOAT16, 2, base,
        dims, strides, box, es,
        CU_TENSOR_MAP_INTERLEAVE_NONE, CU_TENSOR_MAP_SWIZZLE_128B,
        CU_TENSOR_MAP_L2_PROMOTION_L2_128B, CU_TENSOR_MAP_FLOAT_OOB_FILL_NONE);
}

extern "C" void kernel_launch(void* const* d_in, const int* in_sizes, int n_in,
                              void* d_out, int out_size)
{
    const float* x   = (const float*)d_in[0];
    const int*   msk = (const int*)d_in[1];
    const float* Wq  = (const float*)d_in[2];
    const float* bq  = (const float*)d_in[3];
    const float* Wk  = (const float*)d_in[4];
    const float* bk  = (const float*)d_in[5];
    const float* Wv  = (const float*)d_in[6];
    const float* bv  = (const float*)d_in[7];
    const float* Wo  = (const float*)d_in[8];
    const float* bo  = (const float*)d_in[9];
    const float* W1  = (const float*)d_in[10];
    const float* b1  = (const float*)d_in[11];
    const float* W2  = (const float*)d_in[12];
    const float* b2  = (const float*)d_in[13];
    const float* g1  = (const float*)d_in[14];
    const float* be1 = (const float*)d_in[15];
    const float* g2  = (const float*)d_in[16];
    const float* be2 = (const float*)d_in[17];
    float* out = (float*)d_out;

    __nv_bfloat16 *xh, *xl, *qh, *kh, *vh, *vt, *oh, *ol, *hb, *hl, *fh, *fl, *wh, *wl;
    float *f32a, *f32b, *f32c;
    cudaGetSymbolAddress((void**)&xh, g_xh);
    cudaGetSymbolAddress((void**)&xl, g_xl);
    cudaGetSymbolAddress((void**)&qh, g_qh);
    cudaGetSymbolAddress((void**)&kh, g_kh);
    cudaGetSymbolAddress((void**)&vh, g_vh);
    cudaGetSymbolAddress((void**)&vt, g_vt);
    cudaGetSymbolAddress((void**)&oh, g_oh);
    cudaGetSymbolAddress((void**)&ol, g_ol);
    cudaGetSymbolAddress((void**)&hb, g_hb);
    cudaGetSymbolAddress((void**)&hl, g_hl);
    cudaGetSymbolAddress((void**)&fh, g_fh);
    cudaGetSymbolAddress((void**)&fl, g_fl);
    cudaGetSymbolAddress((void**)&wh, g_wh);
    cudaGetSymbolAddress((void**)&wl, g_wl);
    cudaGetSymbolAddress((void**)&f32a, g_f32a);
    cudaGetSymbolAddress((void**)&f32b, g_f32b);
    cudaGetSymbolAddress((void**)&f32c, g_f32c);

    PFN_encodeTiled enc = get_encode_fn();
    CUtensorMap tmXH, tmXL, tmOH, tmOL, tmHB, tmHL, tmFH, tmFL;
    make_map_bf16(enc, &tmXH, xh, DD, MM);
    make_map_bf16(enc, &tmXL, xl, DD, MM);
    make_map_bf16(enc, &tmOH, oh, DD, MM);
    make_map_bf16(enc, &tmOL, ol, DD, MM);
    make_map_bf16(enc, &tmHB, hb, DD, MM);
    make_map_bf16(enc, &tmHL, hl, DD, MM);
    make_map_bf16(enc, &tmFH, fh, FF, MM);
    make_map_bf16(enc, &tmFL, fl, FF, MM);

    cudaFuncSetAttribute(gemm_bf<0>, cudaFuncAttributeMaxDynamicSharedMemorySize, GEMM_SMEM_BYTES);
    cudaFuncSetAttribute(gemm_bf<1>, cudaFuncAttributeMaxDynamicSharedMemorySize, GEMM_SMEM_BYTES);
    cudaFuncSetAttribute(gemm_bf<2>, cudaFuncAttributeMaxDynamicSharedMemorySize, GEMM_SMEM_BYTES);
    cudaFuncSetAttribute(flash_tc_kernel, cudaFuncAttributeMaxDynamicSharedMemorySize, FL_SMEM);

    dim3 blk(256);
    dim3 pw(32, 8);

    split_kernel<<<(size_t)MM * DD / 1024, blk>>>(x, xh, xl);

    prep_w_kernel<<<dim3(DD / 32, DD / 32), pw>>>(Wq, wh + WQ_OFF, wl + WQ_OFF, DD, DD);
    prep_w_kernel<<<dim3(DD / 32, DD / 32), pw>>>(Wk, wh + WK_OFF, wl + WK_OFF, DD, DD);
    prep_w_kernel<<<dim3(DD / 32, DD / 32), pw>>>(Wv, wh + WV_OFF, wl + WV_OFF, DD, DD);
    prep_w_kernel<<<dim3(DD / 32, DD / 32), pw>>>(Wo, wh + WO_OFF, wl + WO_OFF, DD, DD);
    prep_w_kernel<<<dim3(FF / 32, DD / 32), pw>>>(W1, wh + W1_OFF, wl + W1_OFF, DD, FF);
    prep_w_kernel<<<dim3(DD / 32, FF / 32), pw>>>(W2, wh + W2_OFF, wl + W2_OFF, FF, DD);

    // QKV combined (N=3072)
    gemm_bf<2><<<dim3(24, 32), blk, GEMM_SMEM_BYTES>>>(
        tmXH, tmXL, xh, xl, wh + WQ_OFF, wl + WQ_OFF,
        nullptr, nullptr, nullptr, qh, kh, vh, bq, bk, bv, MM, 3 * DD, DD);

    transpose_v_kernel<<<dim3(SS / 64, BB * HH), blk>>>(vh, vt);

    flash_tc_kernel<<<dim3(SS / 128, BB * HH), blk, FL_SMEM>>>(qh, kh, vt, msk, oh, ol);

    // O projection
    gemm_bf<0><<<dim3(8, 32), blk, GEMM_SMEM_BYTES>>>(
        tmOH, tmOL, oh, ol, wh + WO_OFF, wl + WO_OFF,
        f32a, nullptr, nullptr, nullptr, nullptr, nullptr, nullptr, nullptr, nullptr,
        MM, DD, DD);

    add_ln_kernel<true><<<MM, blk>>>(x, f32a, bo, g1, be1, f32b, hb, hl);

    // FFN1
    gemm_bf<1><<<dim3(32, 32), blk, GEMM_SMEM_BYTES>>>(
        tmHB, tmHL, hb, hl, wh + W1_OFF, wl + W1_OFF,
        nullptr, fh, fl, nullptr, nullptr, nullptr, b1, nullptr, nullptr, MM, FF, DD);

    // FFN2
    gemm_bf<0><<<dim3(8, 32), blk, GEMM_SMEM_BYTES>>>(
        tmFH, tmFL, fh, fl, wh + W2_OFF, wl + W2_OFF,
        f32c, nullptr, nullptr, nullptr, nullptr, nullptr, nullptr, nullptr, nullptr,
        MM, DD, FF);

    add_ln_kernel<false><<<MM, blk>>>(f32b, f32c, b2, g2, be2, out, nullptr, nullptr);
}

// round 17
// speedup vs baseline: 1.1193x; 1.0021x over previous
#include <cuda_runtime.h>
#include <cuda.h>
#include <cuda_bf16.h>
#include <math.h>
#include <stdint.h>

constexpr int BB = 4;
constexpr int SS = 2048;
constexpr int DD = 1024;
constexpr int HH = 16;
constexpr int HD = 64;
constexpr int FF = 4096;
constexpr int MM = BB * SS;

#if defined(__CUDA_ARCH_FEAT_SM103_ALL) || defined(__CUDA_ARCH_FEAT_SM100_ALL)
#define HAS_TCGEN05 1
#else
#define HAS_TCGEN05 0
#endif

// ---------------- device scratch ----------------
__device__ __nv_bfloat16 g_xh[(size_t)MM * DD];
__device__ __nv_bfloat16 g_xl[(size_t)MM * DD];
__device__ __nv_bfloat16 g_qh[(size_t)MM * DD];
__device__ __nv_bfloat16 g_kh[(size_t)MM * DD];
__device__ __nv_bfloat16 g_vt[(size_t)MM * DD];   // V transposed [B,H,HD,SS]
__device__ __nv_bfloat16 g_oh[(size_t)MM * DD];
__device__ __nv_bfloat16 g_ol[(size_t)MM * DD];
__device__ __nv_bfloat16 g_hb[(size_t)MM * DD];
__device__ __nv_bfloat16 g_hl[(size_t)MM * DD];
__device__ __nv_bfloat16 g_fh[(size_t)MM * FF];
__device__ __nv_bfloat16 g_fl[(size_t)MM * FF];
__device__ float g_f32a[(size_t)MM * DD];
__device__ float g_f32b[(size_t)MM * DD];
__device__ float g_f32c[(size_t)MM * DD];

constexpr size_t WQ_OFF = 0;
constexpr size_t WK_OFF = 1048576;
constexpr size_t WV_OFF = 2097152;
constexpr size_t WO_OFF = 3145728;
constexpr size_t W1_OFF = 4194304;
constexpr size_t W2_OFF = 8388608;
constexpr size_t WTOT   = 12582912;
__device__ __nv_bfloat16 g_wh[WTOT];
__device__ __nv_bfloat16 g_wl[WTOT];

// ---------------- helpers ----------------
__device__ __forceinline__ uint32_t smem_u32(const void* p) {
    uint32_t a;
    asm("{ .reg .u64 t; cvta.to.shared.u64 t, %1; cvt.u32.u64 %0, t; }" : "=r"(a) : "l"(p));
    return a;
}
__device__ __forceinline__ uint32_t swz128(uint32_t off) { return off ^ ((off >> 3) & 0x70); }
__device__ __forceinline__ uint32_t pack_bf2(__nv_bfloat16 a, __nv_bfloat16 b) {
    __nv_bfloat162 t; t.x = a; t.y = b; return *(uint32_t*)&t;
}
#define CP_ASYNC16(saddr, gptr) \
    asm volatile("cp.async.cg.shared.global [%0], [%1], 16;" \
        :: "r"((uint32_t)(saddr)), "l"(gptr) : "memory")
#define CP_COMMIT() asm volatile("cp.async.commit_group;" ::: "memory")
#define CP_WAIT(n)  asm volatile("cp.async.wait_group %0;" :: "n"(n) : "memory")

#if HAS_TCGEN05
__device__ __forceinline__ uint32_t elect_one_pred() {
    uint32_t pred;
    asm volatile("{\n\t.reg .pred p;\n\telect.sync _|p, 0xFFFFFFFF;\n\tselp.b32 %0, 1, 0, p;\n\t}" : "=r"(pred));
    return pred;
}
__device__ __forceinline__ uint32_t cluster_rank() {
    uint32_t r;
    asm("mov.u32 %0, %%cluster_ctarank;" : "=r"(r));
    return r;
}
#define TCGEN05_ALLOC(smem_addr, nCols) \
    asm volatile("tcgen05.alloc.cta_group::1.sync.aligned.shared::cta.b32 [%0], %1;" \
        :: "r"((uint32_t)(smem_addr)), "r"((uint32_t)(nCols)) : "memory")
#define TCGEN05_DEALLOC(tmem_addr, nCols) \
    asm volatile("tcgen05.dealloc.cta_group::1.sync.aligned.b32 %0, %1;" \
        :: "r"(tmem_addr), "r"((uint32_t)(nCols)))
#define TCGEN05_COMMIT(mbar) \
    asm volatile("tcgen05.commit.cta_group::1.mbarrier::arrive::one.shared::cluster.b64 [%0];" \
        :: "r"((uint32_t)(mbar)) : "memory")
#define TCGEN05_COMMIT_MC(mbar, mask) \
    asm volatile("tcgen05.commit.cta_group::1.mbarrier::arrive::one.shared::cluster.multicast::cluster.b64 [%0], %1;" \
        :: "r"((uint32_t)(mbar)), "h"((uint16_t)(mask)) : "memory")
#define TCGEN05_WAIT_LD()  asm volatile("tcgen05.wait::ld.sync.aligned;" ::: "memory")
#define TCGEN05_FENCE_BEFORE() asm volatile("tcgen05.fence::before_thread_sync;" ::: "memory")
#define TCGEN05_FENCE_AFTER()  asm volatile("tcgen05.fence::after_thread_sync;" ::: "memory")
#define FENCE_ASYNC_SHARED() asm volatile("fence.proxy.async.shared::cta;" ::: "memory")
#define MBARRIER_INIT(mbar, cnt) \
    asm volatile("mbarrier.init.shared.b64 [%0], %1;" :: "r"((uint32_t)(mbar)), "r"((uint32_t)(cnt)) : "memory")
#define MBARRIER_INVAL(mbar) \
    asm volatile("mbarrier.inval.shared.b64 [%0];" :: "r"((uint32_t)(mbar)) : "memory")
#define MBARRIER_EXPECT_TX(mbar, bytes) \
    asm volatile("mbarrier.arrive.expect_tx.shared.b64 _, [%0], %1;" \
        :: "r"((uint32_t)(mbar)), "r"((uint32_t)(bytes)) : "memory")
#define CLUSTER_SYNC() do { \
    asm volatile("barrier.cluster.arrive.aligned;" ::: "memory"); \
    asm volatile("barrier.cluster.wait.aligned;" ::: "memory"); \
} while (0)
#define TMA_LOAD_2D_MC(smem, mapp, cx, cy, mbar, mask) \
    asm volatile("cp.async.bulk.tensor.2d.shared::cluster.global.tile.mbarrier::complete_tx::bytes.multicast::cluster " \
        "[%0], [%1, {%2, %3}], [%4], %5;" \
        :: "r"((uint32_t)(smem)), "l"(mapp), "r"((int)(cx)), "r"((int)(cy)), \
           "r"((uint32_t)(mbar)), "h"((uint16_t)(mask)) : "memory")
#define MBARRIER_WAIT_PARITY(mbar, parity) do {                                    \
    uint32_t _mb = (uint32_t)(mbar);                                               \
    uint32_t _pa = (uint32_t)(parity);                                             \
    uint32_t _done;                                                                \
    asm volatile(                                                                  \
        "{\n\t.reg .pred p;\n\t"                                                   \
        "mbarrier.try_wait.parity.acquire.cta.shared::cta.b64 p, [%1], %2;\n\t"    \
        "selp.b32 %0, 1, 0, p;\n\t}"                                               \
        : "=r"(_done) : "r"(_mb), "r"(_pa) : "memory");                            \
    if (!_done) {                                                                  \
        asm volatile(                                                              \
            "{\n\t.reg .pred P1;\n\t"                                              \
            "WL_%=:\n\t"                                                           \
            "mbarrier.try_wait.parity.acquire.cta.shared::cta.b64 P1, [%0], %1, 0x989680;\n\t" \
            "@P1 bra.uni WD_%=;\n\t"                                               \
            "bra.uni WL_%=;\n\t"                                                   \
            "WD_%=:\n\t}"                                                          \
            :: "r"(_mb), "r"(_pa) : "memory");                                     \
    }                                                                              \
} while (0)
#define TCGEN05_LD_X32(r, addr) \
    asm volatile( \
        "tcgen05.ld.sync.aligned.32x32b.x32.b32 " \
        "{%0, %1, %2, %3, %4, %5, %6, %7, " \
        " %8, %9, %10, %11, %12, %13, %14, %15, " \
        " %16, %17, %18, %19, %20, %21, %22, %23, " \
        " %24, %25, %26, %27, %28, %29, %30, %31}, [%32];" \
        : "=r"((r)[0]),  "=r"((r)[1]),  "=r"((r)[2]),  "=r"((r)[3]), \
          "=r"((r)[4]),  "=r"((r)[5]),  "=r"((r)[6]),  "=r"((r)[7]), \
          "=r"((r)[8]),  "=r"((r)[9]),  "=r"((r)[10]), "=r"((r)[11]), \
          "=r"((r)[12]), "=r"((r)[13]), "=r"((r)[14]), "=r"((r)[15]), \
          "=r"((r)[16]), "=r"((r)[17]), "=r"((r)[18]), "=r"((r)[19]), \
          "=r"((r)[20]), "=r"((r)[21]), "=r"((r)[22]), "=r"((r)[23]), \
          "=r"((r)[24]), "=r"((r)[25]), "=r"((r)[26]), "=r"((r)[27]), \
          "=r"((r)[28]), "=r"((r)[29]), "=r"((r)[30]), "=r"((r)[31]) \
        : "r"(addr))

__device__ __forceinline__ uint64_t make_desc_sw128(uint32_t addr) {
    constexpr uint64_t BASE =
        (uint64_t(2) << 61) | (uint64_t(1) << 46) | (uint64_t(64) << 32) | (uint64_t(1) << 16);
    return BASE | ((uint64_t)(addr >> 4) & 0x3FFF);
}
__device__ __forceinline__ void mma_bf16_ss(uint32_t d, uint64_t ad, uint64_t bd,
                                            uint32_t idesc, bool acc) {
    uint32_t en = acc ? 1u : 0u;
    asm volatile(
        "{\n\t.reg .pred p;\n\t"
        "setp.ne.u32 p, %5, 0;\n\t"
        "tcgen05.mma.cta_group::1.kind::f16 [%0], %1, %2, %3, {%4, %4, %4, %4}, p;\n\t}"
        :: "r"(d), "l"(ad), "l"(bd), "r"(idesc), "r"(0u), "r"(en) : "memory");
}
#endif

constexpr uint32_t GEMM_IDESC =
    (1u << 4) | (1u << 7) | (1u << 10) | ((128 / 8) << 17) | ((128 / 16) << 24);
constexpr uint32_t IDESC_N64 =
    (1u << 4) | (1u << 7) | (1u << 10) | ((64 / 8) << 17) | ((128 / 16) << 24);

// ---------------- weight prep ----------------
__global__ void prep_w_kernel(const float* __restrict__ W,
                              __nv_bfloat16* __restrict__ Bh,
                              __nv_bfloat16* __restrict__ Bl, int K, int N)
{
    __shared__ float t[32][33];
    const int n0 = blockIdx.x * 32, k0 = blockIdx.y * 32;
#pragma unroll
    for (int i = 0; i < 4; i++)
        t[threadIdx.y + i * 8][threadIdx.x] =
            W[(size_t)(k0 + threadIdx.y + i * 8) * N + n0 + threadIdx.x];
    __syncthreads();
#pragma unroll
    for (int i = 0; i < 4; i++) {
        int n = threadIdx.y + i * 8;
        float v = t[threadIdx.x][n];
        __nv_bfloat16 h = __float2bfloat16(v);
        size_t idx = (size_t)(n0 + n) * K + k0 + threadIdx.x;
        Bh[idx] = h;
        Bl[idx] = __float2bfloat16(v - __bfloat162float(h));
    }
}

// fp32 -> bf16 hi/lo split
__global__ __launch_bounds__(256) void split_kernel(
    const float* __restrict__ in,
    __nv_bfloat16* __restrict__ oh, __nv_bfloat16* __restrict__ ol)
{
    size_t i = ((size_t)blockIdx.x * 256 + threadIdx.x) * 4;
    float4 v = *(const float4*)(in + i);
    __nv_bfloat16 h0 = __float2bfloat16(v.x), h1 = __float2bfloat16(v.y);
    __nv_bfloat16 h2 = __float2bfloat16(v.z), h3 = __float2bfloat16(v.w);
    *(uint2*)(oh + i) = make_uint2(pack_bf2(h0, h1), pack_bf2(h2, h3));
    *(uint2*)(ol + i) = make_uint2(
        pack_bf2(__float2bfloat16(v.x - __bfloat162float(h0)),
                 __float2bfloat16(v.y - __bfloat162float(h1))),
        pack_bf2(__float2bfloat16(v.z - __bfloat162float(h2)),
                 __float2bfloat16(v.w - __bfloat162float(h3))));
}

// ---------------------------------------------------------------------------
// GEMM: 256x128 tile, cluster(2,1,1): A via TMA 2D multicast, B via cp.async.
// EPI 2: QKV; V (mat==2) written DIRECTLY transposed into vt [BH][HD][SS].
// ---------------------------------------------------------------------------
constexpr int GEMM_STAGE = 98304;
constexpr int GEMM_SMEM_BYTES = 2 * GEMM_STAGE + 1024;

template <int EPI>
__global__ __launch_bounds__(256, 1) __cluster_dims__(2, 1, 1) void gemm_bf(
    const __grid_constant__ CUtensorMap tmAh, const __grid_constant__ CUtensorMap tmAl,
    const __nv_bfloat16* __restrict__ Ah, const __nv_bfloat16* __restrict__ Al,
    const __nv_bfloat16* __restrict__ Bh, const __nv_bfloat16* __restrict__ Bl,
    float* __restrict__ Cf, __nv_bfloat16* __restrict__ Ch, __nv_bfloat16* __restrict__ Cl,
    __nv_bfloat16* __restrict__ D0, __nv_bfloat16* __restrict__ D1, __nv_bfloat16* __restrict__ D2,
    const float* __restrict__ bias0, const float* __restrict__ bias1, const float* __restrict__ bias2,
    int M, int N, int K)
{
    extern __shared__ char dsmem[];
    uintptr_t p = ((uintptr_t)dsmem + 1023) & ~(uintptr_t)1023;
    char* buf = (char*)p;
    const int tid = threadIdx.x;
    const int wid = tid >> 5;
    const int lane = tid & 31;
    const int m0 = blockIdx.y << 8;
    const int n0 = blockIdx.x << 7;

#if HAS_TCGEN05
    __shared__ alignas(16) unsigned long long ctrlq[6];
    const uint32_t sbuf = smem_u32(buf);
    const uint32_t ctrl = smem_u32(ctrlq);
    const uint32_t xr = cluster_rank();

    if (wid == 0) TCGEN05_ALLOC(ctrl, 256);
    if (tid == 0) {
        MBARRIER_INIT(ctrl + 8, 2);
        MBARRIER_INIT(ctrl + 16, 2);
        MBARRIER_INIT(ctrl + 24, 1);
        MBARRIER_INIT(ctrl + 32, 1);
        MBARRIER_INIT(ctrl + 40, 1);
    }
    __syncthreads();
    CLUSTER_SYNC();
    uint32_t tmem;
    asm volatile("ld.shared.b32 %0, [%1];" : "=r"(tmem) : "r"(ctrl));

    const int NC = K >> 6;

    auto load_chunk = [&](int ck, int st) {
        const uint32_t sb = sbuf + (uint32_t)st * GEMM_STAGE;
        const int k0 = ck << 6;
        if (tid == 0) {
            MBARRIER_EXPECT_TX(ctrl + 32 + st * 8, 65536);
            TMA_LOAD_2D_MC(sb + xr * 16384, &tmAh, k0, m0 + xr * 128,
                           ctrl + 32 + st * 8, 0x3);
            TMA_LOAD_2D_MC(sb + 32768 + xr * 16384, &tmAl, k0, m0 + xr * 128,
                           ctrl + 32 + st * 8, 0x3);
        }
#pragma unroll
        for (int j = 0; j < 4; j++) {
            int u = tid + j * 256;
            int r = u >> 3, g = u & 7;
            uint32_t so = swz128((uint32_t)(r * 128 + g * 16));
            size_t bo = (size_t)(n0 + r) * K + k0 + g * 8;
            CP_ASYNC16(sb + 65536 + so, Bh + bo);
            CP_ASYNC16(sb + 81920 + so, Bl + bo);
        }
    };

    load_chunk(0, 0);
    CP_COMMIT();
    load_chunk(1, 1);
    CP_COMMIT();

    int ph[2] = {0, 0};
    int phD[2] = {0, 0};

    for (int i = 0; i < NC; i++) {
        const int st = i & 1;
        MBARRIER_WAIT_PARITY(ctrl + 32 + st * 8, phD[st]);
        phD[st] ^= 1;
        if (i < NC - 1) CP_WAIT(1);
        else            CP_WAIT(0);
        __syncthreads();
        FENCE_ASYNC_SHARED();

        if (wid == 0 && elect_one_pred()) {
            const uint32_t sb = sbuf + (uint32_t)st * GEMM_STAGE;
            uint64_t dBh = make_desc_sw128(sb + 65536);
            uint64_t dBl = make_desc_sw128(sb + 81920);
#pragma unroll
            for (int mt = 0; mt < 2; mt++) {
                uint64_t dAh = make_desc_sw128(sb + mt * 16384);
                uint64_t dAl = make_desc_sw128(sb + 32768 + mt * 16384);
                uint32_t dst = tmem + mt * 128;
#pragma unroll
                for (int ks = 0; ks < 4; ks++)
                    mma_bf16_ss(dst, dAh + ks * 2, dBh + ks * 2, GEMM_IDESC, !(i == 0 && ks == 0));
#pragma unroll
                for (int ks = 0; ks < 4; ks++)
                    mma_bf16_ss(dst, dAl + ks * 2, dBh + ks * 2, GEMM_IDESC, true);
#pragma unroll
                for (int ks = 0; ks < 4; ks++)
                    mma_bf16_ss(dst, dAh + ks * 2, dBl + ks * 2, GEMM_IDESC, true);
            }
            TCGEN05_COMMIT_MC(ctrl + 8 + st * 8, 0x3);
        }

        if (i + 2 < NC) {
            MBARRIER_WAIT_PARITY(ctrl + 8 + st * 8, ph[st]);
            ph[st] ^= 1;
            load_chunk(i + 2, st);
            CP_COMMIT();
        }
    }

    if (wid == 0 && elect_one_pred()) TCGEN05_COMMIT(ctrl + 24);
    MBARRIER_WAIT_PARITY(ctrl + 24, 0);
    TCGEN05_FENCE_AFTER();

    {
        const int sp = wid & 3;
        const int chf = wid >> 2;
#pragma unroll
        for (int mt = 0; mt < 2; mt++) {
            uint32_t r[64];
            TCGEN05_LD_X32(r, tmem + mt * 128 + chf * 64);
            TCGEN05_LD_X32(r + 32, tmem + mt * 128 + chf * 64 + 32);
            TCGEN05_WAIT_LD();
            TCGEN05_FENCE_BEFORE();

            const int row = m0 + mt * 128 + sp * 32 + lane;
            const int c0 = n0 + chf * 64;

            if (EPI == 0) {
                float* cp = Cf + (size_t)row * N + c0;
#pragma unroll
                for (int c = 0; c < 16; c++) {
                    float4 v;
                    v.x = __uint_as_float(r[4 * c + 0]);
                    v.y = __uint_as_float(r[4 * c + 1]);
                    v.z = __uint_as_float(r[4 * c + 2]);
                    v.w = __uint_as_float(r[4 * c + 3]);
                    *(float4*)(cp + 4 * c) = v;
                }
            } else if (EPI == 1) {
                size_t base = (size_t)row * N + c0;
#pragma unroll
                for (int j8 = 0; j8 < 8; j8++) {
                    uint32_t hw[4], lw[4];
#pragma unroll
                    for (int q = 0; q < 4; q++) {
                        int j = j8 * 8 + q * 2;
                        float v0 = fmaxf(__uint_as_float(r[j])     + bias0[c0 + j],     0.0f);
                        float v1 = fmaxf(__uint_as_float(r[j + 1]) + bias0[c0 + j + 1], 0.0f);
                        __nv_bfloat16 h0 = __float2bfloat16(v0), h1 = __float2bfloat16(v1);
                        hw[q] = pack_bf2(h0, h1);
                        lw[q] = pack_bf2(__float2bfloat16(v0 - __bfloat162float(h0)),
                                         __float2bfloat16(v1 - __bfloat162float(h1)));
                    }
                    *(uint4*)(Ch + base + j8 * 8) = make_uint4(hw[0], hw[1], hw[2], hw[3]);
                    *(uint4*)(Cl + base + j8 * 8) = make_uint4(lw[0], lw[1], lw[2], lw[3]);
                }
            } else {
                const int mat = c0 >> 10;
                const int lc = c0 & 1023;
                const float* bs = (mat == 0) ? bias0 : (mat == 1) ? bias1 : bias2;
                const int h_ = lc >> 6;
                const int b_ = row >> 11;
                const int s_ = row & (SS - 1);
                if (mat < 2) {
                    __nv_bfloat16* Dd = (mat == 0) ? D0 : D1;
                    size_t base = (((size_t)b_ * HH + h_) * SS + s_) * HD;
#pragma unroll
                    for (int j8 = 0; j8 < 8; j8++) {
                        uint32_t hw[4];
#pragma unroll
                        for (int q = 0; q < 4; q++) {
                            int j = j8 * 8 + q * 2;
                            float v0 = __uint_as_float(r[j])     + bs[lc + j];
                            float v1 = __uint_as_float(r[j + 1]) + bs[lc + j + 1];
                            hw[q] = pack_bf2(__float2bfloat16(v0), __float2bfloat16(v1));
                        }
                        *(uint4*)(Dd + base + j8 * 8) = make_uint4(hw[0], hw[1], hw[2], hw[3]);
                    }
                } else {
                    // V: write transposed into vt [BH][HD][SS]
                    size_t vbase = ((size_t)(b_ * HH + h_)) * HD;
#pragma unroll
                    for (int j = 0; j < 32; j++) {
                        float v0 = __uint_as_float(r[2 * j])     + bs[lc + 2 * j];
                        float v1 = __uint_as_float(r[2 * j + 1]) + bs[lc + 2 * j + 1];
                        D2[(vbase + 2 * j) * SS + s_]     = __float2bfloat16(v0);
                        D2[(vbase + 2 * j + 1) * SS + s_] = __float2bfloat16(v1);
                    }
                }
            }
        }
    }

    __syncthreads();
    if (tid == 0) {
        MBARRIER_INVAL(ctrl + 8);
        MBARRIER_INVAL(ctrl + 16);
        MBARRIER_INVAL(ctrl + 24);
        MBARRIER_INVAL(ctrl + 32);
        MBARRIER_INVAL(ctrl + 40);
    }
    __syncthreads();
    if (wid == 0) TCGEN05_DEALLOC(tmem, 256);
    CLUSTER_SYNC();

#else  // FFMA fallback
    float* As = (float*)buf;
    float* Bs = As + 16 * 132;
    const int tx = tid & 15, ty = tid >> 4;
    for (int mt = 0; mt < 2; mt++) {
        const int mb = m0 + mt * 128;
        float acc[8][8];
#pragma unroll
        for (int i = 0; i < 8; i++)
#pragma unroll
            for (int j = 0; j < 8; j++) acc[i][j] = 0.0f;
        for (int k0 = 0; k0 < K; k0 += 16) {
            for (int it = 0; it < 8; it++) {
                int idx = tid + it * 256;
                int rr = idx >> 4, kk = idx & 15;
                As[kk * 132 + rr] =
                    __bfloat162float(Ah[(size_t)(mb + rr) * K + k0 + kk]) +
                    __bfloat162float(Al[(size_t)(mb + rr) * K + k0 + kk]);
                Bs[kk * 132 + rr] =
                    __bfloat162float(Bh[(size_t)(n0 + rr) * K + k0 + kk]) +
                    __bfloat162float(Bl[(size_t)(n0 + rr) * K + k0 + kk]);
            }
            __syncthreads();
#pragma unroll
            for (int k = 0; k < 16; k++) {
                float a[8], bb[8];
#pragma unroll
                for (int i = 0; i < 8; i++) a[i] = As[k * 132 + ty * 8 + i];
#pragma unroll
                for (int j = 0; j < 8; j++) bb[j] = Bs[k * 132 + tx * 8 + j];
#pragma unroll
                for (int i = 0; i < 8; i++)
#pragma unroll
                    for (int j = 0; j < 8; j++) acc[i][j] = fmaf(a[i], bb[j], acc[i][j]);
            }
            __syncthreads();
        }
#pragma unroll
        for (int i = 0; i < 8; i++) {
            int row = mb + ty * 8 + i;
#pragma unroll
            for (int j = 0; j < 8; j++) {
                int col = n0 + tx * 8 + j;
                float v = acc[i][j];
                if (EPI == 0) {
                    Cf[(size_t)row * N + col] = v;
                } else if (EPI == 1) {
                    v = fmaxf(v + bias0[col], 0.0f);
                    __nv_bfloat16 h = __float2bfloat16(v);
                    Ch[(size_t)row * N + col] = h;
                    Cl[(size_t)row * N + col] = __float2bfloat16(v - __bfloat162float(h));
                } else {
                    int mat = col >> 10, lc = col & 1023;
                    const float* bs = (mat == 0) ? bias0 : (mat == 1) ? bias1 : bias2;
                    float vv = v + bs[lc];
                    int h_ = lc >> 6, d = lc & 63;
                    int b_ = row >> 11, s_ = row & (SS - 1);
                    if (mat < 2) {
                        __nv_bfloat16* Dd = (mat == 0) ? D0 : D1;
                        Dd[(((size_t)b_ * HH + h_) * SS + s_) * HD + d] = __float2bfloat16(vv);
                    } else {
                        D2[(((size_t)(b_ * HH + h_)) * HD + d) * SS + s_] = __float2bfloat16(vv);
                    }
                }
            }
        }
        __syncthreads();
    }
#endif
}

// ---------------------------------------------------------------------------
// Pipelined tcgen05 flash attention; S_{k+1} issued BEFORE exp of iter k.
// ---------------------------------------------------------------------------
constexpr int FL_Q  = 0;
constexpr int FL_K  = 16384;
constexpr int FL_VT = 65536;
constexpr int FL_P  = 114688;
constexpr int FL_MS = 147456;
constexpr int FL_CT = 155648;
constexpr int FL_SMEM = FL_CT + 64 + 1024 + 1024;
constexpr int NKB = SS / 128;

__global__ __launch_bounds__(256, 1) void flash_tc_kernel(
    const __nv_bfloat16* __restrict__ qg, const __nv_bfloat16* __restrict__ kg,
    const __nv_bfloat16* __restrict__ vt, const int* __restrict__ mask,
    __nv_bfloat16* __restrict__ outh, __nv_bfloat16* __restrict__ outl)
{
    extern __shared__ char dsmem[];
    uintptr_t pb = ((uintptr_t)dsmem + 1023) & ~(uintptr_t)1023;
    char* buf = (char*)pb;
    const int tid = threadIdx.x;
    const int wid = tid >> 5;
    const int lane = tid & 31;
    const int bh = blockIdx.y;
    const int b_ = bh >> 4;
    const int h_ = bh & (HH - 1);
    const int q0 = blockIdx.x * 128;

#if HAS_TCGEN05
    const int sp = wid & 3;
    const int chf = wid >> 2;
    const uint32_t sbuf = smem_u32(buf);
    const uint32_t ctrl = sbuf + FL_CT;
    int* msk_s = (int*)(buf + FL_MS);
    float* lpart = (float*)(buf + FL_CT + 64);

    if (wid == 0) TCGEN05_ALLOC(ctrl, 512);
    if (tid == 0) { MBARRIER_INIT(ctrl + 8, 1); MBARRIER_INIT(ctrl + 16, 1); }
    __syncthreads();
    uint32_t tmem;
    asm volatile("ld.shared.b32 %0, [%1];" : "=r"(tmem) : "r"(ctrl));

    auto load_kv = [&](int kb, int st) {
        const uint32_t sbK = sbuf + FL_K + (uint32_t)st * 16384;
        const uint32_t sbV = sbuf + FL_VT + (uint32_t)st * 16384;
#pragma unroll
        for (int j = 0; j < 4; j++) {
            int u = tid + j * 256;
            int r = u >> 3, g = u & 7;
            CP_ASYNC16(sbK + swz128((uint32_t)(r * 128 + g * 16)),
                       kg + ((size_t)(bh * SS + kb * 128 + r)) * HD + g * 8);
        }
#pragma unroll
        for (int j = 0; j < 4; j++) {
            int u = tid + j * 256;
            int d = u >> 4, g = u & 15;
            int key0 = g * 8;
            uint32_t o = (uint32_t)(((key0 >> 6) * 8 + (d >> 3)) * 1024 + (d & 7) * 128 + (key0 & 63) * 2);
            CP_ASYNC16(sbV + swz128(o),
                       vt + ((size_t)(bh * HD + d)) * SS + kb * 128 + key0);
        }
    };

#pragma unroll
    for (int j = 0; j < 4; j++) {
        int u = tid + j * 256;
        int r = u >> 3, g = u & 7;
        CP_ASYNC16(sbuf + FL_Q + swz128((uint32_t)(r * 128 + g * 16)),
                   qg + ((size_t)(bh * SS + q0 + r)) * HD + g * 8);
    }
#pragma unroll
    for (int j = 0; j < 2; j++)
        CP_ASYNC16(sbuf + FL_MS + tid * 16 + j * 4096,
                   mask + b_ * SS + tid * 4 + j * 1024);
    load_kv(0, 0);
    CP_COMMIT();
    load_kv(1, 1);
    CP_COMMIT();

    const uint64_t dQ = make_desc_sw128(sbuf + FL_Q);
    const uint64_t dP = make_desc_sw128(sbuf + FL_P);
    const int pOff[8] = {0, 2, 4, 6, 1024, 1026, 1028, 1030};
    const int vOff[8] = {0, 2, 4, 6, 512, 514, 516, 518};

    CP_WAIT(1);
    __syncthreads();
    FENCE_ASYNC_SHARED();
    if (wid == 0 && elect_one_pred()) {
        uint64_t dK = make_desc_sw128(sbuf + FL_K);
#pragma unroll
        for (int s = 0; s < 4; s++)
            mma_bf16_ss(tmem, dQ + s * 2, dK + s * 2, GEMM_IDESC, s != 0);
        TCGEN05_COMMIT(ctrl + 8);
    }

    float lsum = 0.0f;
    int phS = 0, phO = 0;
    const int r = sp * 32 + lane;

    for (int k = 0; k < NKB; k++) {
        const int st = k % 3;
        const uint32_t sbase = (uint32_t)(k & 1) * 128;

        // wait S_k
        MBARRIER_WAIT_PARITY(ctrl + 8, phS);
        phS ^= 1;
        TCGEN05_FENCE_AFTER();

        // EARLY S_{k+1}: drain pending K/V loads, issue before exp of iter k
        if (k + 1 < NKB) {
            CP_WAIT(0);
            __syncthreads();
            FENCE_ASYNC_SHARED();
            if (wid == 0 && elect_one_pred()) {
                uint64_t dK = make_desc_sw128(sbuf + FL_K + (uint32_t)((k + 1) % 3) * 16384);
                uint32_t dst = tmem + ((k + 1) & 1) * 128;
#pragma unroll
                for (int s = 0; s < 4; s++)
                    mma_bf16_ss(dst, dQ + s * 2, dK + s * 2, GEMM_IDESC, s != 0);
                TCGEN05_COMMIT(ctrl + 8);
            }
        }

        // LDTM S_k (both halves, single wait) + exp
        uint32_t sr[64];
        TCGEN05_LD_X32(sr, tmem + sbase + chf * 64);
        TCGEN05_LD_X32(sr + 32, tmem + sbase + chf * 64 + 32);
        TCGEN05_WAIT_LD();

        uint32_t ppk[32];
        const int cbase = k * 128 + chf * 64;
#pragma unroll
        for (int j = 0; j < 32; j++) {
            float p0 = msk_s[cbase + 2 * j]     ? __expf(__uint_as_float(sr[2 * j])     * 0.125f) : 0.0f;
            float p1 = msk_s[cbase + 2 * j + 1] ? __expf(__uint_as_float(sr[2 * j + 1]) * 0.125f) : 0.0f;
            __nv_bfloat16 bp0 = __float2bfloat16(p0), bp1 = __float2bfloat16(p1);
            ppk[j] = pack_bf2(bp0, bp1);
            lsum += __bfloat162float(bp0) + __bfloat162float(bp1);
        }

        // wait PV_{k-1}: frees P buffer and stage (k+2)%3
        if (k > 0) { MBARRIER_WAIT_PARITY(ctrl + 16, phO); phO ^= 1; }
        if (k + 2 < NKB) { load_kv(k + 2, (k + 2) % 3); CP_COMMIT(); }

        // write P
#pragma unroll
        for (int h2 = 0; h2 < 2; h2++) {
            uint32_t pbo = (uint32_t)((chf * 16 + (r >> 3)) * 1024 + (r & 7) * 128 + h2 * 64);
#pragma unroll
            for (int j = 0; j < 4; j++)
                *(uint4*)(buf + FL_P + swz128(pbo + j * 16)) =
                    make_uint4(ppk[h2 * 16 + 4 * j], ppk[h2 * 16 + 4 * j + 1],
                               ppk[h2 * 16 + 4 * j + 2], ppk[h2 * 16 + 4 * j + 3]);
        }
        TCGEN05_FENCE_BEFORE();
        FENCE_ASYNC_SHARED();
        __syncthreads();

        // PV_k
        if (wid == 0 && elect_one_pred()) {
            uint64_t dVT = make_desc_sw128(sbuf + FL_VT + (uint32_t)st * 16384);
#pragma unroll
            for (int s = 0; s < 8; s++)
                mma_bf16_ss(tmem + 256, dP + pOff[s], dVT + vOff[s], IDESC_N64,
                            !(k == 0 && s == 0));
            TCGEN05_COMMIT(ctrl + 16);
        }
    }

    MBARRIER_WAIT_PARITY(ctrl + 16, phO);
    TCGEN05_FENCE_AFTER();
    lpart[chf * 128 + r] = lsum;
    __syncthreads();

    if (wid < 4) {
        uint32_t orr[64];
        TCGEN05_LD_X32(orr, tmem + 256);
        TCGEN05_LD_X32(orr + 32, tmem + 288);
        TCGEN05_WAIT_LD();
        TCGEN05_FENCE_BEFORE();
        float inv = 1.0f / (lpart[r] + lpart[128 + r]);
        size_t base = ((size_t)(b_ * SS + q0 + r)) * DD + h_ * HD;
#pragma unroll
        for (int j8 = 0; j8 < 8; j8++) {
            uint32_t hw[4], lw[4];
#pragma unroll
            for (int q = 0; q < 4; q++) {
                int j = j8 * 8 + q * 2;
                float v0 = __uint_as_float(orr[j])     * inv;
                float v1 = __uint_as_float(orr[j + 1]) * inv;
                __nv_bfloat16 h0 = __float2bfloat16(v0), h1 = __float2bfloat16(v1);
                hw[q] = pack_bf2(h0, h1);
                lw[q] = pack_bf2(__float2bfloat16(v0 - __bfloat162float(h0)),
                                 __float2bfloat16(v1 - __bfloat162float(h1)));
            }
            *(uint4*)(outh + base + j8 * 8) = make_uint4(hw[0], hw[1], hw[2], hw[3]);
            *(uint4*)(outl + base + j8 * 8) = make_uint4(lw[0], lw[1], lw[2], lw[3]);
        }
    }
    __syncthreads();
    if (tid == 0) { MBARRIER_INVAL(ctrl + 8); MBARRIER_INVAL(ctrl + 16); }
    __syncthreads();
    if (wid == 0) TCGEN05_DEALLOC(tmem, 512);
#else
    if (tid < 128) {
        int rr = q0 + tid;
        float qr[64], o[64], l = 0.0f;
        for (int d = 0; d < 64; d++) {
            qr[d] = __bfloat162float(qg[((size_t)(bh * SS + rr)) * HD + d]);
            o[d] = 0.0f;
        }
        for (int key = 0; key < SS; key++) {
            if (!mask[b_ * SS + key]) continue;
            float s = 0.0f;
            const __nv_bfloat16* kp = kg + ((size_t)(bh * SS + key)) * HD;
            for (int d = 0; d < 64; d++) s += qr[d] * __bfloat162float(kp[d]);
            float pw = __expf(s * 0.125f);
            l += pw;
            for (int d = 0; d < 64; d++)
                o[d] += pw * __bfloat162float(vt[((size_t)(bh * HD + d)) * SS + key]);
        }
        float inv = 1.0f / l;
        for (int d = 0; d < 64; d++) {
            float v = o[d] * inv;
            __nv_bfloat16 h = __float2bfloat16(v);
            size_t od = ((size_t)(b_ * SS + rr)) * DD + h_ * HD + d;
            outh[od] = h;
            outl[od] = __float2bfloat16(v - __bfloat162float(h));
        }
    }
#endif
}

// ---------------- residual + bias + LN ----------------
template <bool SPLIT>
__global__ __launch_bounds__(256) void add_ln_kernel(
    const float* __restrict__ a, const float* __restrict__ b,
    const float* __restrict__ bias,
    const float* __restrict__ g, const float* __restrict__ be,
    float* __restrict__ out,
    __nv_bfloat16* __restrict__ oh, __nv_bfloat16* __restrict__ ol)
{
    __shared__ float sh[10];
    const int row = blockIdx.x;
    const int tid = threadIdx.x;
    const int wid = tid >> 5, lane = tid & 31;
    const size_t base = (size_t)row * DD + tid * 4;

    float4 av = *(const float4*)(a + base);
    float4 bv = *(const float4*)(b + base);
    float4 cv = *(const float4*)(bias + tid * 4);
    float4 t = make_float4(av.x + bv.x + cv.x, av.y + bv.y + cv.y,
                           av.z + bv.z + cv.z, av.w + bv.w + cv.w);
    float s = t.x + t.y + t.z + t.w;
#pragma unroll
    for (int off = 16; off >= 1; off >>= 1) s += __shfl_xor_sync(0xffffffffu, s, off);
    if (lane == 0) sh[wid] = s;
    __syncthreads();
    if (tid == 0) {
        float t2 = 0.f;
#pragma unroll
        for (int w = 0; w < 8; w++) t2 += sh[w];
        sh[8] = t2 * (1.0f / 1024.0f);
    }
    __syncthreads();
    float mu = sh[8];
    float dx = t.x - mu, dy = t.y - mu, dz = t.z - mu, dw = t.w - mu;
    float sq = dx * dx + dy * dy + dz * dz + dw * dw;
#pragma unroll
    for (int off = 16; off >= 1; off >>= 1) sq += __shfl_xor_sync(0xffffffffu, sq, off);
    if (lane == 0) sh[wid] = sq;
    __syncthreads();
    if (tid == 0) {
        float t2 = 0.f;
#pragma unroll
        for (int w = 0; w < 8; w++) t2 += sh[w];
        sh[9] = rsqrtf(t2 * (1.0f / 1024.0f) + 1e-5f);
    }
    __syncthreads();
    float inv = sh[9];
    float4 gv = *(const float4*)(g + tid * 4);
    float4 bev = *(const float4*)(be + tid * 4);
    float4 r = make_float4(dx * inv * gv.x + bev.x, dy * inv * gv.y + bev.y,
                           dz * inv * gv.z + bev.z, dw * inv * gv.w + bev.w);
    *(float4*)(out + base) = r;
    if (SPLIT) {
        __nv_bfloat16 h0 = __float2bfloat16(r.x), h1 = __float2bfloat16(r.y);
        __nv_bfloat16 h2 = __float2bfloat16(r.z), h3 = __float2bfloat16(r.w);
        *(uint2*)(oh + base) = make_uint2(pack_bf2(h0, h1), pack_bf2(h2, h3));
        *(uint2*)(ol + base) = make_uint2(
            pack_bf2(__float2bfloat16(r.x - __bfloat162float(h0)),
                     __float2bfloat16(r.y - __bfloat162float(h1))),
            pack_bf2(__float2bfloat16(r.z - __bfloat162float(h2)),
                     __float2bfloat16(r.w - __bfloat162float(h3))));
    }
}

// ---------------------------------------------------------------------------
typedef CUresult (*PFN_encodeTiled)(
    CUtensorMap*, CUtensorMapDataType, cuuint32_t, void*,
    const cuuint64_t*, const cuuint64_t*, const cuuint32_t*, const cuuint32_t*,
    CUtensorMapInterleave, CUtensorMapSwizzle, CUtensorMapL2promotion,
    CUtensorMapFloatOOBfill);

static PFN_encodeTiled get_encode_fn() {
    void* fn = nullptr;
    cudaDriverEntryPointQueryResult st;
#if CUDART_VERSION >= 12000
    cudaGetDriverEntryPoint("cuTensorMapEncodeTiled", &fn, cudaEnableDefault, &st);
#else
    cudaGetDriverEntryPoint("cuTensorMapEncodeTiled", &fn, cudaEnableDefault);
#endif
    return (PFN_encodeTiled)fn;
}

static void make_map_bf16(PFN_encodeTiled enc, CUtensorMap* m, void* base,
                          uint64_t K, uint64_t rows) {
    cuuint64_t dims[2] = {K, rows};
    cuuint64_t strides[1] = {K * 2};
    cuuint32_t box[2] = {64, 128};
    cuuint32_t es[2] = {1, 1};
    enc(m, CU_TENSOR_MAP_DATA_TYPE_BFLOAT16, 2, base,
        dims, strides, box, es,
        CU_TENSOR_MAP_INTERLEAVE_NONE, CU_TENSOR_MAP_SWIZZLE_128B,
        CU_TENSOR_MAP_L2_PROMOTION_L2_128B, CU_TENSOR_MAP_FLOAT_OOB_FILL_NONE);
}

extern "C" void kernel_launch(void* const* d_in, const int* in_sizes, int n_in,
                              void* d_out, int out_size)
{
    const float* x   = (const float*)d_in[0];
    const int*   msk = (const int*)d_in[1];
    const float* Wq  = (const float*)d_in[2];
    const float* bq  = (const float*)d_in[3];
    const float* Wk  = (const float*)d_in[4];
    const float* bk  = (const float*)d_in[5];
    const float* Wv  = (const float*)d_in[6];
    const float* bv  = (const float*)d_in[7];
    const float* Wo  = (const float*)d_in[8];
    const float* bo  = (const float*)d_in[9];
    const float* W1  = (const float*)d_in[10];
    const float* b1  = (const float*)d_in[11];
    const float* W2  = (const float*)d_in[12];
    const float* b2  = (const float*)d_in[13];
    const float* g1  = (const float*)d_in[14];
    const float* be1 = (const float*)d_in[15];
    const float* g2  = (const float*)d_in[16];
    const float* be2 = (const float*)d_in[17];
    float* out = (float*)d_out;

    __nv_bfloat16 *xh, *xl, *qh, *kh, *vt, *oh, *ol, *hb, *hl, *fh, *fl, *wh, *wl;
    float *f32a, *f32b, *f32c;
    cudaGetSymbolAddress((void**)&xh, g_xh);
    cudaGetSymbolAddress((void**)&xl, g_xl);
    cudaGetSymbolAddress((void**)&qh, g_qh);
    cudaGetSymbolAddress((void**)&kh, g_kh);
    cudaGetSymbolAddress((void**)&vt, g_vt);
    cudaGetSymbolAddress((void**)&oh, g_oh);
    cudaGetSymbolAddress((void**)&ol, g_ol);
    cudaGetSymbolAddress((void**)&hb, g_hb);
    cudaGetSymbolAddress((void**)&hl, g_hl);
    cudaGetSymbolAddress((void**)&fh, g_fh);
    cudaGetSymbolAddress((void**)&fl, g_fl);
    cudaGetSymbolAddress((void**)&wh, g_wh);
    cudaGetSymbolAddress((void**)&wl, g_wl);
    cudaGetSymbolAddress((void**)&f32a, g_f32a);
    cudaGetSymbolAddress((void**)&f32b, g_f32b);
    cudaGetSymbolAddress((void**)&f32c, g_f32c);

    PFN_encodeTiled enc = get_encode_fn();
    CUtensorMap tmXH, tmXL, tmOH, tmOL, tmHB, tmHL, tmFH, tmFL;
    make_map_bf16(enc, &tmXH, xh, DD, MM);
    make_map_bf16(enc, &tmXL, xl, DD, MM);
    make_map_bf16(enc, &tmOH, oh, DD, MM);
    make_map_bf16(enc, &tmOL, ol, DD, MM);
    make_map_bf16(enc, &tmHB, hb, DD, MM);
    make_map_bf16(enc, &tmHL, hl, DD, MM);
    make_map_bf16(enc, &tmFH, fh, FF, MM);
    make_map_bf16(enc, &tmFL, fl, FF, MM);

    cudaFuncSetAttribute(gemm_bf<0>, cudaFuncAttributeMaxDynamicSharedMemorySize, GEMM_SMEM_BYTES);
    cudaFuncSetAttribute(gemm_bf<1>, cudaFuncAttributeMaxDynamicSharedMemorySize, GEMM_SMEM_BYTES);
    cudaFuncSetAttribute(gemm_bf<2>, cudaFuncAttributeMaxDynamicSharedMemorySize, GEMM_SMEM_BYTES);
    cudaFuncSetAttribute(flash_tc_kernel, cudaFuncAttributeMaxDynamicSharedMemorySize, FL_SMEM);

    dim3 blk(256);
    dim3 pw(32, 8);

    split_kernel<<<(size_t)MM * DD / 1024, blk>>>(x, xh, xl);

    prep_w_kernel<<<dim3(DD / 32, DD / 32), pw>>>(Wq, wh + WQ_OFF, wl + WQ_OFF, DD, DD);
    prep_w_kernel<<<dim3(DD / 32, DD / 32), pw>>>(Wk, wh + WK_OFF, wl + WK_OFF, DD, DD);
    prep_w_kernel<<<dim3(DD / 32, DD / 32), pw>>>(Wv, wh + WV_OFF, wl + WV_OFF, DD, DD);
    prep_w_kernel<<<dim3(DD / 32, DD / 32), pw>>>(Wo, wh + WO_OFF, wl + WO_OFF, DD, DD);
    prep_w_kernel<<<dim3(FF / 32, DD / 32), pw>>>(W1, wh + W1_OFF, wl + W1_OFF, DD, FF);
    prep_w_kernel<<<dim3(DD / 32, FF / 32), pw>>>(W2, wh + W2_OFF, wl + W2_OFF, FF, DD);

    // QKV combined (N=3072); V written directly transposed into vt
    gemm_bf<2><<<dim3(24, 32), blk, GEMM_SMEM_BYTES>>>(
        tmXH, tmXL, xh, xl, wh + WQ_OFF, wl + WQ_OFF,
        nullptr, nullptr, nullptr, qh, kh, vt, bq, bk, bv, MM, 3 * DD, DD);

    flash_tc_kernel<<<dim3(SS / 128, BB * HH), blk, FL_SMEM>>>(qh, kh, vt, msk, oh, ol);

    // O projection
    gemm_bf<0><<<dim3(8, 32), blk, GEMM_SMEM_BYTES>>>(
        tmOH, tmOL, oh, ol, wh + WO_OFF, wl + WO_OFF,
        f32a, nullptr, nullptr, nullptr, nullptr, nullptr, nullptr, nullptr, nullptr,
        MM, DD, DD);

    add_ln_kernel<true><<<MM, blk>>>(x, f32a, bo, g1, be1, f32b, hb, hl);

    // FFN1
    gemm_bf<1><<<dim3(32, 32), blk, GEMM_SMEM_BYTES>>>(
        tmHB, tmHL, hb, hl, wh + W1_OFF, wl + W1_OFF,
        nullptr, fh, fl, nullptr, nullptr, nullptr, b1, nullptr, nullptr, MM, FF, DD);

    // FFN2
    gemm_bf<0><<<dim3(8, 32), blk, GEMM_SMEM_BYTES>>>(
        tmFH, tmFL, fh, fl, wh + W2_OFF, wl + W2_OFF,
        f32c, nullptr, nullptr, nullptr, nullptr, nullptr, nullptr, nullptr, nullptr,
        MM, DD, FF);

    add_ln_kernel<false><<<MM, blk>>>(f32b, f32c, b2, g2, be2, out, nullptr, nullptr);
}